// round 12
// baseline (speedup 1.0000x reference)
#include <cuda_runtime.h>
#include <cuda_bf16.h>
#include <cstdint>

#define BD 4096
#define ID 1024
#define PD 512
#define FD 2048
#define K2 4096

#define SMEM12 (3 * 32768)   // 3 stages x (16KB A + 16KB B)
#define SMEM3  (4 * 24576)   // 4 stages x (16KB A(hi|lo) + 8KB B(hi|lo))

// ---------------- scratch (device globals; allocation-free) ----------------
__device__ __align__(256) __nv_bfloat16 g_xh[(size_t)BD*ID];
__device__ __align__(256) __nv_bfloat16 g_xl[(size_t)BD*ID];
__device__ __align__(256) __nv_bfloat16 g_fh[(size_t)FD*ID];
__device__ __align__(256) __nv_bfloat16 g_fl[(size_t)FD*ID];
__device__ __align__(256) __nv_bfloat16 g_ph[(size_t)PD*ID];
__device__ __align__(256) __nv_bfloat16 g_pl[(size_t)PD*ID];
__device__ __align__(256) __nv_bfloat16 g_Ah[(size_t)BD*K2];  // [u^2 | u] hi
__device__ __align__(256) __nv_bfloat16 g_Al[(size_t)BD*K2];  // lo
__device__ __align__(256) __nv_bfloat16 g_Ch[(size_t)PD*K2];  // [th*v^2+al*v | be*v^2] hi
__device__ __align__(256) __nv_bfloat16 g_Cl[(size_t)PD*K2];  // lo
__device__ float g_su[BD];   // raw sum_f u^2
__device__ float g_sv[PD];   // raw sum_f v^2

// ---------------- PTX helpers ----------------
__device__ __forceinline__ uint32_t smem_u32(const void* p) {
    uint32_t a;
    asm("{ .reg .u64 t; cvta.to.shared.u64 t, %1; cvt.u32.u64 %0, t; }" : "=r"(a) : "l"(p));
    return a;
}
__device__ __forceinline__ void cp16(uint32_t dst, const void* src) {
    asm volatile("cp.async.cg.shared.global [%0], [%1], 16;" :: "r"(dst), "l"(src));
}
__device__ __forceinline__ void cp_commit() { asm volatile("cp.async.commit_group;" ::: "memory"); }
template<int N> __device__ __forceinline__ void cp_wait() {
    asm volatile("cp.async.wait_group %0;" :: "n"(N) : "memory");
}
__device__ __forceinline__ void ldsm4(uint32_t (&r)[4], uint32_t addr) {
    asm volatile("ldmatrix.sync.aligned.m8n8.x4.shared.b16 {%0,%1,%2,%3}, [%4];"
        : "=r"(r[0]), "=r"(r[1]), "=r"(r[2]), "=r"(r[3]) : "r"(addr));
}
__device__ __forceinline__ void mma16816(float* d, const uint32_t* a, uint32_t b0, uint32_t b1) {
    asm volatile("mma.sync.aligned.m16n8k16.row.col.f32.bf16.bf16.f32 "
        "{%0,%1,%2,%3}, {%4,%5,%6,%7}, {%8,%9}, {%0,%1,%2,%3};"
        : "+f"(d[0]), "+f"(d[1]), "+f"(d[2]), "+f"(d[3])
        : "r"(a[0]), "r"(a[1]), "r"(a[2]), "r"(a[3]), "r"(b0), "r"(b1));
}

// ---------------- vectorized split conversion + accumulator zero ----------
__global__ __launch_bounds__(256) void split_all(const float* __restrict__ x,
                                                 const float* __restrict__ f,
                                                 const float* __restrict__ p)
{
    const int t = blockIdx.x * 256 + threadIdx.x;
    const size_t i = (size_t)t * 8;
    constexpr size_t N1 = (size_t)BD * ID;
    constexpr size_t N2 = N1 + (size_t)FD * ID;
    const float* src; __nv_bfloat16 *hp, *lp; size_t j;
    if (i < N1)      { j = i;      src = x; hp = g_xh; lp = g_xl; }
    else if (i < N2) { j = i - N1; src = f; hp = g_fh; lp = g_fl; }
    else             { j = i - N2; src = p; hp = g_ph; lp = g_pl; }

    float4 v0 = *reinterpret_cast<const float4*>(src + j);
    float4 v1 = *reinterpret_cast<const float4*>(src + j + 4);
    float vv[8] = {v0.x, v0.y, v0.z, v0.w, v1.x, v1.y, v1.z, v1.w};
    __nv_bfloat16 hh[8], ll[8];
    #pragma unroll
    for (int k = 0; k < 8; k++) {
        hh[k] = __float2bfloat16(vv[k]);
        ll[k] = __float2bfloat16(vv[k] - __bfloat162float(hh[k]));
    }
    *reinterpret_cast<uint4*>(hp + j) = *reinterpret_cast<const uint4*>(hh);
    *reinterpret_cast<uint4*>(lp + j) = *reinterpret_cast<const uint4*>(ll);

    if (t < BD) g_su[t] = 0.0f;
    if (t < PD) g_sv[t] = 0.0f;
}

__device__ __forceinline__ void split2(float a, float b, __nv_bfloat162& h, __nv_bfloat162& l) {
    __nv_bfloat16 ha = __float2bfloat16(a);
    __nv_bfloat16 hb = __float2bfloat16(b);
    h.x = ha; h.y = hb;
    l.x = __float2bfloat16(a - __bfloat162float(ha));
    l.y = __float2bfloat16(b - __bfloat162float(hb));
}

// ---------------------------------------------------------------------------
// Fused GEMM1+GEMM2: 128x128xBK64, 3 sequential split passes, SINGLE-SYNC
// multistage mainloop (wait -> sync -> load freed stage -> compute).
// bid <  512 : MODE0  x @ f^T -> relu -> g_A split [u^2|u], atomic sum u^2
// bid >= 512 : MODE1  p @ f^T -> relu -> g_C split, atomic sum v^2
// ---------------------------------------------------------------------------
__global__ void __launch_bounds__(256, 2)
tv_gemm12(const float* __restrict__ alpha_p,
          const float* __restrict__ beta_p,
          const float* __restrict__ theta_p)
{
    constexpr int K  = ID;
    constexpr int KT = K / 64;
    constexpr int T  = 3 * KT;

    extern __shared__ __align__(1024) char smem[];
    const uint32_t sb = smem_u32(smem);
    const int tid  = threadIdx.x;
    const int lane = tid & 31, wid = tid >> 5;
    const int wm = wid >> 2, wn = wid & 3;          // 2 x 4 warp grid

    const int bid   = blockIdx.x;
    const int mode1 = (bid >= 512);
    const int lbid  = mode1 ? bid - 512 : bid;
    const int bx    = lbid & 15;
    const int by    = lbid >> 4;

    const __nv_bfloat16* Ahi = (mode1 ? g_ph : g_xh) + (size_t)by * 128 * K;
    const __nv_bfloat16* Alo = (mode1 ? g_pl : g_xl) + (size_t)by * 128 * K;
    const __nv_bfloat16* Bhi = g_fh + (size_t)bx * 128 * K;
    const __nv_bfloat16* Blo = g_fl + (size_t)bx * 128 * K;

    float acc[4][4][4];
    #pragma unroll
    for (int a = 0; a < 4; a++)
        #pragma unroll
        for (int b = 0; b < 4; b++)
            #pragma unroll
            for (int c = 0; c < 4; c++) acc[a][b][c] = 0.0f;

    auto load_tiles = [&](int i) {
        const int p  = i / KT;
        const int k0 = (i - p * KT) << 6;
        const __nv_bfloat16* As = (p == 2) ? Alo : Ahi;
        const __nv_bfloat16* Bs = (p == 1) ? Blo : Bhi;
        const uint32_t base = sb + (i % 3) * 32768;
        #pragma unroll
        for (int it = 0; it < 4; it++) {
            const int idx = (it << 8) + tid;          // 0..1023
            const int r = idx >> 3, c = idx & 7;
            const uint32_t sw = (uint32_t)((c ^ (r & 7)) << 4);
            cp16(base + r * 128 + sw,         As + (size_t)r * K + k0 + (c << 3));
            cp16(base + 16384 + r * 128 + sw, Bs + (size_t)r * K + k0 + (c << 3));
        }
    };

    load_tiles(0); cp_commit();
    load_tiles(1); cp_commit();

    for (int i = 0; i < T; i++) {
        // single-sync multistage: wait for stage i, barrier, refill freed stage
        if (i + 2 < T) {
            cp_wait<1>(); __syncthreads();
            load_tiles(i + 2); cp_commit();
        } else if (i + 1 < T) {
            cp_wait<1>(); __syncthreads();
        } else {
            cp_wait<0>(); __syncthreads();
        }

        const uint32_t Ab = sb + (i % 3) * 32768;
        const uint32_t Bb = Ab + 16384;

        #pragma unroll
        for (int ks = 0; ks < 4; ks++) {
            uint32_t afr[4][4], bfr[2][4];
            #pragma unroll
            for (int mt = 0; mt < 4; mt++) {
                const int r  = wm * 64 + mt * 16 + (lane & 15);
                const int cb = (ks << 1) + (lane >> 4);
                ldsm4(afr[mt], Ab + r * 128 + ((cb ^ (r & 7)) << 4));
            }
            #pragma unroll
            for (int np = 0; np < 2; np++) {
                const int g  = lane >> 3;
                const int r  = wn * 32 + np * 16 + ((g & 2) << 2) + (lane & 7);
                const int cb = (ks << 1) + (g & 1);
                ldsm4(bfr[np], Bb + r * 128 + ((cb ^ (r & 7)) << 4));
            }
            #pragma unroll
            for (int mt = 0; mt < 4; mt++)
                #pragma unroll
                for (int nt = 0; nt < 4; nt++)
                    mma16816(acc[mt][nt], afr[mt],
                             bfr[nt >> 1][(nt & 1) * 2], bfr[nt >> 1][(nt & 1) * 2 + 1]);
        }
    }

    // ---------------- epilogue: split-store + fused row-sum atomics --------
    float al_ = 0.f, be = 0.f, th = 0.f;
    if (mode1) { al_ = *alpha_p; be = *beta_p; th = *theta_p; }

    float rs[4][2];
    #pragma unroll
    for (int mt = 0; mt < 4; mt++) { rs[mt][0] = 0.0f; rs[mt][1] = 0.0f; }

    #pragma unroll
    for (int mt = 0; mt < 4; mt++) {
        const size_t rbase = (size_t)by * 128 + wm * 64 + mt * 16 + (lane >> 2);
        #pragma unroll
        for (int nt = 0; nt < 4; nt++) {
            const int c = bx * 128 + wn * 32 + nt * 8 + ((lane & 3) << 1);
            #pragma unroll
            for (int h = 0; h < 2; h++) {
                const float v0 = fmaxf(acc[mt][nt][h * 2 + 0], 0.0f);
                const float v1 = fmaxf(acc[mt][nt][h * 2 + 1], 0.0f);
                const float q0 = v0 * v0, q1 = v1 * v1;
                rs[mt][h] += q0 + q1;
                const size_t rb = (rbase + h * 8) * (size_t)K2;
                __nv_bfloat162 hh, ll;
                if (!mode1) {
                    split2(q0, q1, hh, ll);
                    *reinterpret_cast<__nv_bfloat162*>(&g_Ah[rb + c]) = hh;
                    *reinterpret_cast<__nv_bfloat162*>(&g_Al[rb + c]) = ll;
                    split2(v0, v1, hh, ll);
                    *reinterpret_cast<__nv_bfloat162*>(&g_Ah[rb + FD + c]) = hh;
                    *reinterpret_cast<__nv_bfloat162*>(&g_Al[rb + FD + c]) = ll;
                } else {
                    split2(fmaf(th, q0, al_ * v0), fmaf(th, q1, al_ * v1), hh, ll);
                    *reinterpret_cast<__nv_bfloat162*>(&g_Ch[rb + c]) = hh;
                    *reinterpret_cast<__nv_bfloat162*>(&g_Cl[rb + c]) = ll;
                    split2(be * q0, be * q1, hh, ll);
                    *reinterpret_cast<__nv_bfloat162*>(&g_Ch[rb + FD + c]) = hh;
                    *reinterpret_cast<__nv_bfloat162*>(&g_Cl[rb + FD + c]) = ll;
                }
            }
        }
    }

    float* sums = mode1 ? g_sv : g_su;
    #pragma unroll
    for (int mt = 0; mt < 4; mt++)
        #pragma unroll
        for (int h = 0; h < 2; h++) {
            float v = rs[mt][h];
            v += __shfl_xor_sync(0xffffffffu, v, 1);
            v += __shfl_xor_sync(0xffffffffu, v, 2);
            if ((lane & 3) == 0) {
                const int row = by * 128 + wm * 64 + mt * 16 + (lane >> 2) + h * 8;
                atomicAdd(&sums[row], v);
            }
        }
}

// ---------------------------------------------------------------------------
// GEMM3 (fused hi/lo, 4-stage, SINGLE-SYNC): 128(M) x 64(N), K=4096, BK=32
// chunks, 3 MMA sets per chunk. out = acc - alpha*su[row] - beta*sv[col]
// ---------------------------------------------------------------------------
__global__ void __launch_bounds__(256, 2)
tv_gemm3(float* __restrict__ out,
         const float* __restrict__ alpha_p,
         const float* __restrict__ beta_p)
{
    constexpr int K = K2;
    constexpr int T = K / 32;          // 128 chunks

    extern __shared__ __align__(1024) char smem[];
    const uint32_t sb = smem_u32(smem);
    const int tid  = threadIdx.x;
    const int lane = tid & 31, wid = tid >> 5;
    const int wm = wid >> 1, wn = wid & 1;          // 4 x 2 warp grid (32x32 warp tile)

    const int bx = blockIdx.x;                      // 8 N-tiles
    const int by = blockIdx.y;                      // 32 M-tiles

    const __nv_bfloat16* Ahi = g_Ah + (size_t)by * 128 * K;
    const __nv_bfloat16* Alo = g_Al + (size_t)by * 128 * K;
    const __nv_bfloat16* Bhi = g_Ch + (size_t)bx * 64 * K;
    const __nv_bfloat16* Blo = g_Cl + (size_t)bx * 64 * K;

    float acc[2][4][4];
    #pragma unroll
    for (int a = 0; a < 2; a++)
        #pragma unroll
        for (int b = 0; b < 4; b++)
            #pragma unroll
            for (int c = 0; c < 4; c++) acc[a][b][c] = 0.0f;

    auto load_tiles = [&](int i) {
        const int k0 = i << 5;
        const uint32_t base = sb + (i & 3) * 24576;
        #pragma unroll
        for (int it = 0; it < 4; it++) {            // A: 1024 chunk-slots
            const int idx = (it << 8) + tid;
            const int r = idx >> 3, c = idx & 7;
            const uint32_t sw = (uint32_t)((c ^ (r & 7)) << 4);
            cp16(base + r * 128 + sw, (c < 4 ? Ahi : Alo) + (size_t)r * K + k0 + ((c & 3) << 3));
        }
        #pragma unroll
        for (int it = 0; it < 2; it++) {            // B: 512 chunk-slots
            const int idx = (it << 8) + tid;
            const int r = idx >> 3, c = idx & 7;
            const uint32_t sw = (uint32_t)((c ^ (r & 7)) << 4);
            cp16(base + 16384 + r * 128 + sw, (c < 4 ? Bhi : Blo) + (size_t)r * K + k0 + ((c & 3) << 3));
        }
    };

    load_tiles(0); cp_commit();
    load_tiles(1); cp_commit();
    load_tiles(2); cp_commit();

    for (int i = 0; i < T; i++) {
        if (i + 3 < T) {
            cp_wait<2>(); __syncthreads();
            load_tiles(i + 3); cp_commit();
        } else if (i + 2 < T) {
            cp_wait<2>(); __syncthreads();
        } else if (i + 1 < T) {
            cp_wait<1>(); __syncthreads();
        } else {
            cp_wait<0>(); __syncthreads();
        }

        const uint32_t Ab = sb + (i & 3) * 24576;
        const uint32_t Bb = Ab + 16384;

        #pragma unroll
        for (int ks = 0; ks < 2; ks++) {
            uint32_t ah[2][4], al[2][4], bh[2][4], bl[2][4];
            #pragma unroll
            for (int mt = 0; mt < 2; mt++) {
                const int r  = wm * 32 + mt * 16 + (lane & 15);
                const int cb = (ks << 1) + (lane >> 4);
                ldsm4(ah[mt], Ab + r * 128 + (((cb)     ^ (r & 7)) << 4));
                ldsm4(al[mt], Ab + r * 128 + (((cb | 4) ^ (r & 7)) << 4));
            }
            #pragma unroll
            for (int np = 0; np < 2; np++) {
                const int g  = lane >> 3;
                const int r  = wn * 32 + np * 16 + ((g & 2) << 2) + (lane & 7);
                const int cb = (ks << 1) + (g & 1);
                ldsm4(bh[np], Bb + r * 128 + (((cb)     ^ (r & 7)) << 4));
                ldsm4(bl[np], Bb + r * 128 + (((cb | 4) ^ (r & 7)) << 4));
            }
            #pragma unroll
            for (int mt = 0; mt < 2; mt++)
                #pragma unroll
                for (int nt = 0; nt < 4; nt++) {
                    uint32_t bh0 = bh[nt >> 1][(nt & 1) * 2], bh1 = bh[nt >> 1][(nt & 1) * 2 + 1];
                    uint32_t bl0 = bl[nt >> 1][(nt & 1) * 2], bl1 = bl[nt >> 1][(nt & 1) * 2 + 1];
                    mma16816(acc[mt][nt], ah[mt], bh0, bh1);
                    mma16816(acc[mt][nt], ah[mt], bl0, bl1);
                    mma16816(acc[mt][nt], al[mt], bh0, bh1);
                }
        }
    }

    const float al_ = *alpha_p, be = *beta_p;

    #pragma unroll
    for (int mt = 0; mt < 2; mt++) {
        const size_t r1 = (size_t)by * 128 + wm * 32 + mt * 16 + (lane >> 2);
        const size_t r2 = r1 + 8;
        const float s1 = al_ * g_su[r1], s2 = al_ * g_su[r2];
        #pragma unroll
        for (int nt = 0; nt < 4; nt++) {
            const int c = bx * 64 + wn * 32 + nt * 8 + ((lane & 3) << 1);
            const float sv0 = be * g_sv[c], sv1 = be * g_sv[c + 1];
            const float* d = acc[mt][nt];
            float2 o1 = make_float2(d[0] - s1 - sv0, d[1] - s1 - sv1);
            float2 o2 = make_float2(d[2] - s2 - sv0, d[3] - s2 - sv1);
            *reinterpret_cast<float2*>(&out[r1 * PD + c]) = o1;
            *reinterpret_cast<float2*>(&out[r2 * PD + c]) = o2;
        }
    }
}

// ---------------------------------------------------------------------------
extern "C" void kernel_launch(void* const* d_in, const int* in_sizes, int n_in,
                              void* d_out, int out_size)
{
    const float* x      = (const float*)d_in[0];  // [4096, 1024]
    const float* feats  = (const float*)d_in[1];  // [2048, 1024]
    const float* protos = (const float*)d_in[2];  // [512, 1024]
    const float* alpha  = (const float*)d_in[3];
    const float* beta   = (const float*)d_in[4];
    const float* theta  = (const float*)d_in[5];
    float* out = (float*)d_out;                   // [4096, 512]

    cudaFuncSetAttribute(tv_gemm12, cudaFuncAttributeMaxDynamicSharedMemorySize, SMEM12);
    cudaFuncSetAttribute(tv_gemm3,  cudaFuncAttributeMaxDynamicSharedMemorySize, SMEM3);

    constexpr int NTOT = BD * ID + FD * ID + PD * ID;   // multiple of 2048
    split_all<<<NTOT / 2048, 256>>>(x, feats, protos);

    tv_gemm12<<<576, 256, SMEM12>>>(alpha, beta, theta);
    tv_gemm3<<<dim3(8, 32), 256, SMEM3>>>(out, alpha, beta);
}

// round 13
// speedup vs baseline: 1.8812x; 1.8812x over previous
#include <cuda_runtime.h>
#include <cuda_bf16.h>
#include <cstdint>

#define BD 4096
#define ID 1024
#define PD 512
#define FD 2048
#define K2 4096

#define SMEM12 (3 * 32768)   // 3 stages x (16KB A + 16KB B)
#define SMEM3  (3 * 32768)   // 3 stages x (16KB A-hi + 8KB Bh + 8KB Bl)

// ---------------- scratch (device globals; allocation-free) ----------------
__device__ __align__(256) __nv_bfloat16 g_xh[(size_t)BD*ID];
__device__ __align__(256) __nv_bfloat16 g_xl[(size_t)BD*ID];
__device__ __align__(256) __nv_bfloat16 g_fh[(size_t)FD*ID];
__device__ __align__(256) __nv_bfloat16 g_fl[(size_t)FD*ID];
__device__ __align__(256) __nv_bfloat16 g_ph[(size_t)PD*ID];
__device__ __align__(256) __nv_bfloat16 g_pl[(size_t)PD*ID];
__device__ __align__(256) __nv_bfloat16 g_Ah[(size_t)BD*K2];  // [u^2 | u] hi ONLY
__device__ __align__(256) __nv_bfloat16 g_Ch[(size_t)PD*K2];  // [th*v^2+al*v | be*v^2] hi
__device__ __align__(256) __nv_bfloat16 g_Cl[(size_t)PD*K2];  // lo
__device__ float g_su[BD];   // raw sum_f u^2
__device__ float g_sv[PD];   // raw sum_f v^2

// ---------------- PTX helpers ----------------
__device__ __forceinline__ uint32_t smem_u32(const void* p) {
    uint32_t a;
    asm("{ .reg .u64 t; cvta.to.shared.u64 t, %1; cvt.u32.u64 %0, t; }" : "=r"(a) : "l"(p));
    return a;
}
__device__ __forceinline__ void cp16(uint32_t dst, const void* src) {
    asm volatile("cp.async.cg.shared.global [%0], [%1], 16;" :: "r"(dst), "l"(src));
}
__device__ __forceinline__ void cp_commit() { asm volatile("cp.async.commit_group;" ::: "memory"); }
template<int N> __device__ __forceinline__ void cp_wait() {
    asm volatile("cp.async.wait_group %0;" :: "n"(N) : "memory");
}
__device__ __forceinline__ void ldsm4(uint32_t (&r)[4], uint32_t addr) {
    asm volatile("ldmatrix.sync.aligned.m8n8.x4.shared.b16 {%0,%1,%2,%3}, [%4];"
        : "=r"(r[0]), "=r"(r[1]), "=r"(r[2]), "=r"(r[3]) : "r"(addr));
}
__device__ __forceinline__ void mma16816(float* d, const uint32_t* a, uint32_t b0, uint32_t b1) {
    asm volatile("mma.sync.aligned.m16n8k16.row.col.f32.bf16.bf16.f32 "
        "{%0,%1,%2,%3}, {%4,%5,%6,%7}, {%8,%9}, {%0,%1,%2,%3};"
        : "+f"(d[0]), "+f"(d[1]), "+f"(d[2]), "+f"(d[3])
        : "r"(a[0]), "r"(a[1]), "r"(a[2]), "r"(a[3]), "r"(b0), "r"(b1));
}

// ---------------- vectorized split conversion + accumulator zero ----------
__global__ __launch_bounds__(256) void split_all(const float* __restrict__ x,
                                                 const float* __restrict__ f,
                                                 const float* __restrict__ p)
{
    const int t = blockIdx.x * 256 + threadIdx.x;
    const size_t i = (size_t)t * 8;
    constexpr size_t N1 = (size_t)BD * ID;
    constexpr size_t N2 = N1 + (size_t)FD * ID;
    const float* src; __nv_bfloat16 *hp, *lp; size_t j;
    if (i < N1)      { j = i;      src = x; hp = g_xh; lp = g_xl; }
    else if (i < N2) { j = i - N1; src = f; hp = g_fh; lp = g_fl; }
    else             { j = i - N2; src = p; hp = g_ph; lp = g_pl; }

    float4 v0 = *reinterpret_cast<const float4*>(src + j);
    float4 v1 = *reinterpret_cast<const float4*>(src + j + 4);
    float vv[8] = {v0.x, v0.y, v0.z, v0.w, v1.x, v1.y, v1.z, v1.w};
    __nv_bfloat16 hh[8], ll[8];
    #pragma unroll
    for (int k = 0; k < 8; k++) {
        hh[k] = __float2bfloat16(vv[k]);
        ll[k] = __float2bfloat16(vv[k] - __bfloat162float(hh[k]));
    }
    *reinterpret_cast<uint4*>(hp + j) = *reinterpret_cast<const uint4*>(hh);
    *reinterpret_cast<uint4*>(lp + j) = *reinterpret_cast<const uint4*>(ll);

    if (t < BD) g_su[t] = 0.0f;
    if (t < PD) g_sv[t] = 0.0f;
}

__device__ __forceinline__ void split2(float a, float b, __nv_bfloat162& h, __nv_bfloat162& l) {
    __nv_bfloat16 ha = __float2bfloat16(a);
    __nv_bfloat16 hb = __float2bfloat16(b);
    h.x = ha; h.y = hb;
    l.x = __float2bfloat16(a - __bfloat162float(ha));
    l.y = __float2bfloat16(b - __bfloat162float(hb));
}

// ---------------------------------------------------------------------------
// Fused GEMM1+GEMM2 (R11-proven loop): 128x128xBK64, 3 sequential split passes.
// bid <  512 : MODE0  x @ f^T -> relu -> g_Ah [u^2|u] (hi only), atomic sum u^2
// bid >= 512 : MODE1  p @ f^T -> relu -> g_C split hi+lo, atomic sum v^2
// ---------------------------------------------------------------------------
__global__ void __launch_bounds__(256, 2)
tv_gemm12(const float* __restrict__ alpha_p,
          const float* __restrict__ beta_p,
          const float* __restrict__ theta_p)
{
    constexpr int K  = ID;
    constexpr int KT = K / 64;
    constexpr int T  = 3 * KT;

    extern __shared__ __align__(1024) char smem[];
    const uint32_t sb = smem_u32(smem);
    const int tid  = threadIdx.x;
    const int lane = tid & 31, wid = tid >> 5;
    const int wm = wid >> 2, wn = wid & 3;          // 2 x 4 warp grid

    const int bid   = blockIdx.x;
    const int mode1 = (bid >= 512);
    const int lbid  = mode1 ? bid - 512 : bid;
    const int bx    = lbid & 15;
    const int by    = lbid >> 4;

    const __nv_bfloat16* Ahi = (mode1 ? g_ph : g_xh) + (size_t)by * 128 * K;
    const __nv_bfloat16* Alo = (mode1 ? g_pl : g_xl) + (size_t)by * 128 * K;
    const __nv_bfloat16* Bhi = g_fh + (size_t)bx * 128 * K;
    const __nv_bfloat16* Blo = g_fl + (size_t)bx * 128 * K;

    float acc[4][4][4];
    #pragma unroll
    for (int a = 0; a < 4; a++)
        #pragma unroll
        for (int b = 0; b < 4; b++)
            #pragma unroll
            for (int c = 0; c < 4; c++) acc[a][b][c] = 0.0f;

    auto load_tiles = [&](int i) {
        const int p  = i / KT;
        const int k0 = (i - p * KT) << 6;
        const __nv_bfloat16* As = (p == 2) ? Alo : Ahi;
        const __nv_bfloat16* Bs = (p == 1) ? Blo : Bhi;
        const uint32_t base = sb + (i % 3) * 32768;
        #pragma unroll
        for (int it = 0; it < 4; it++) {
            const int idx = (it << 8) + tid;          // 0..1023
            const int r = idx >> 3, c = idx & 7;
            const uint32_t sw = (uint32_t)((c ^ (r & 7)) << 4);
            cp16(base + r * 128 + sw,         As + (size_t)r * K + k0 + (c << 3));
            cp16(base + 16384 + r * 128 + sw, Bs + (size_t)r * K + k0 + (c << 3));
        }
    };

    load_tiles(0); cp_commit();
    load_tiles(1); cp_commit();

    for (int i = 0; i < T; i++) {
        if (i + 2 < T)      { load_tiles(i + 2); cp_commit(); cp_wait<2>(); }
        else if (i + 1 < T) { cp_wait<1>(); }
        else                { cp_wait<0>(); }
        __syncthreads();

        const uint32_t Ab = sb + (i % 3) * 32768;
        const uint32_t Bb = Ab + 16384;

        #pragma unroll
        for (int ks = 0; ks < 4; ks++) {
            uint32_t afr[4][4], bfr[2][4];
            #pragma unroll
            for (int mt = 0; mt < 4; mt++) {
                const int r  = wm * 64 + mt * 16 + (lane & 15);
                const int cb = (ks << 1) + (lane >> 4);
                ldsm4(afr[mt], Ab + r * 128 + ((cb ^ (r & 7)) << 4));
            }
            #pragma unroll
            for (int np = 0; np < 2; np++) {
                const int g  = lane >> 3;
                const int r  = wn * 32 + np * 16 + ((g & 2) << 2) + (lane & 7);
                const int cb = (ks << 1) + (g & 1);
                ldsm4(bfr[np], Bb + r * 128 + ((cb ^ (r & 7)) << 4));
            }
            #pragma unroll
            for (int mt = 0; mt < 4; mt++)
                #pragma unroll
                for (int nt = 0; nt < 4; nt++)
                    mma16816(acc[mt][nt], afr[mt],
                             bfr[nt >> 1][(nt & 1) * 2], bfr[nt >> 1][(nt & 1) * 2 + 1]);
        }
        __syncthreads();
    }

    // ---------------- epilogue: store + fused row-sum atomics --------------
    float al_ = 0.f, be = 0.f, th = 0.f;
    if (mode1) { al_ = *alpha_p; be = *beta_p; th = *theta_p; }

    float rs[4][2];
    #pragma unroll
    for (int mt = 0; mt < 4; mt++) { rs[mt][0] = 0.0f; rs[mt][1] = 0.0f; }

    #pragma unroll
    for (int mt = 0; mt < 4; mt++) {
        const size_t rbase = (size_t)by * 128 + wm * 64 + mt * 16 + (lane >> 2);
        #pragma unroll
        for (int nt = 0; nt < 4; nt++) {
            const int c = bx * 128 + wn * 32 + nt * 8 + ((lane & 3) << 1);
            #pragma unroll
            for (int h = 0; h < 2; h++) {
                const float v0 = fmaxf(acc[mt][nt][h * 2 + 0], 0.0f);
                const float v1 = fmaxf(acc[mt][nt][h * 2 + 1], 0.0f);
                const float q0 = v0 * v0, q1 = v1 * v1;
                rs[mt][h] += q0 + q1;
                const size_t rb = (rbase + h * 8) * (size_t)K2;
                if (!mode1) {
                    // hi-only stores (A-side lo term dropped in GEMM3)
                    __nv_bfloat162 hh;
                    hh.x = __float2bfloat16(q0); hh.y = __float2bfloat16(q1);
                    *reinterpret_cast<__nv_bfloat162*>(&g_Ah[rb + c]) = hh;
                    hh.x = __float2bfloat16(v0); hh.y = __float2bfloat16(v1);
                    *reinterpret_cast<__nv_bfloat162*>(&g_Ah[rb + FD + c]) = hh;
                } else {
                    __nv_bfloat162 hh, ll;
                    split2(fmaf(th, q0, al_ * v0), fmaf(th, q1, al_ * v1), hh, ll);
                    *reinterpret_cast<__nv_bfloat162*>(&g_Ch[rb + c]) = hh;
                    *reinterpret_cast<__nv_bfloat162*>(&g_Cl[rb + c]) = ll;
                    split2(be * q0, be * q1, hh, ll);
                    *reinterpret_cast<__nv_bfloat162*>(&g_Ch[rb + FD + c]) = hh;
                    *reinterpret_cast<__nv_bfloat162*>(&g_Cl[rb + FD + c]) = ll;
                }
            }
        }
    }

    float* sums = mode1 ? g_sv : g_su;
    #pragma unroll
    for (int mt = 0; mt < 4; mt++)
        #pragma unroll
        for (int h = 0; h < 2; h++) {
            float v = rs[mt][h];
            v += __shfl_xor_sync(0xffffffffu, v, 1);
            v += __shfl_xor_sync(0xffffffffu, v, 2);
            if ((lane & 3) == 0) {
                const int row = by * 128 + wm * 64 + mt * 16 + (lane >> 2) + h * 8;
                atomicAdd(&sums[row], v);
            }
        }
}

// ---------------------------------------------------------------------------
// GEMM3 (A-lo dropped): 128(M) x 64(N), K=4096, BK=64 chunks.
// Per chunk: 2 MMA sets (ah*bh, ah*bl) into one accumulator. 3-stage pipeline.
// out = acc - alpha*su[row] - beta*sv[col]
// ---------------------------------------------------------------------------
__global__ void __launch_bounds__(256, 2)
tv_gemm3(float* __restrict__ out,
         const float* __restrict__ alpha_p,
         const float* __restrict__ beta_p)
{
    constexpr int K = K2;
    constexpr int T = K / 64;          // 64 chunks

    extern __shared__ __align__(1024) char smem[];
    const uint32_t sb = smem_u32(smem);
    const int tid  = threadIdx.x;
    const int lane = tid & 31, wid = tid >> 5;
    const int wm = wid >> 1, wn = wid & 1;          // 4 x 2 warp grid (32x32 warp tile)

    const int bx = blockIdx.x;                      // 8 N-tiles
    const int by = blockIdx.y;                      // 32 M-tiles

    const __nv_bfloat16* Ahi = g_Ah + (size_t)by * 128 * K;
    const __nv_bfloat16* Bhi = g_Ch + (size_t)bx * 64 * K;
    const __nv_bfloat16* Blo = g_Cl + (size_t)bx * 64 * K;

    float acc[2][4][4];
    #pragma unroll
    for (int a = 0; a < 2; a++)
        #pragma unroll
        for (int b = 0; b < 4; b++)
            #pragma unroll
            for (int c = 0; c < 4; c++) acc[a][b][c] = 0.0f;

    // stage: [A-hi 128x128B | Bh 64x128B | Bl 64x128B] = 32KB
    auto load_tiles = [&](int i) {
        const int k0 = i << 6;
        const uint32_t base = sb + (i % 3) * 32768;
        #pragma unroll
        for (int it = 0; it < 4; it++) {            // A: 1024 chunk-slots
            const int idx = (it << 8) + tid;
            const int r = idx >> 3, c = idx & 7;
            const uint32_t sw = (uint32_t)((c ^ (r & 7)) << 4);
            cp16(base + r * 128 + sw, Ahi + (size_t)r * K + k0 + (c << 3));
        }
        #pragma unroll
        for (int it = 0; it < 4; it++) {            // B: 512 bh + 512 bl slots
            const int idx = (it << 8) + tid;        // 0..1023
            const int half = idx >> 9;              // 0 = bh, 1 = bl
            const int li   = idx & 511;
            const int r = li >> 3, c = li & 7;
            const uint32_t sw = (uint32_t)((c ^ (r & 7)) << 4);
            const __nv_bfloat16* Bs = half ? Blo : Bhi;
            cp16(base + 16384 + half * 8192 + r * 128 + sw,
                 Bs + (size_t)r * K + k0 + (c << 3));
        }
    };

    load_tiles(0); cp_commit();
    load_tiles(1); cp_commit();

    for (int i = 0; i < T; i++) {
        if (i + 2 < T)      { load_tiles(i + 2); cp_commit(); cp_wait<2>(); }
        else if (i + 1 < T) { cp_wait<1>(); }
        else                { cp_wait<0>(); }
        __syncthreads();

        const uint32_t Ab  = sb + (i % 3) * 32768;
        const uint32_t Bhb = Ab + 16384;
        const uint32_t Blb = Ab + 16384 + 8192;

        #pragma unroll
        for (int ks = 0; ks < 4; ks++) {
            uint32_t afr[2][4], bh[2][4], bl[2][4];
            #pragma unroll
            for (int mt = 0; mt < 2; mt++) {
                const int r  = wm * 32 + mt * 16 + (lane & 15);
                const int cb = (ks << 1) + (lane >> 4);
                ldsm4(afr[mt], Ab + r * 128 + ((cb ^ (r & 7)) << 4));
            }
            #pragma unroll
            for (int np = 0; np < 2; np++) {
                const int g  = lane >> 3;
                const int r  = wn * 32 + np * 16 + ((g & 2) << 2) + (lane & 7);
                const int cb = (ks << 1) + (g & 1);
                const uint32_t off = r * 128 + ((cb ^ (r & 7)) << 4);
                ldsm4(bh[np], Bhb + off);
                ldsm4(bl[np], Blb + off);
            }
            #pragma unroll
            for (int mt = 0; mt < 2; mt++)
                #pragma unroll
                for (int nt = 0; nt < 4; nt++) {
                    mma16816(acc[mt][nt], afr[mt],
                             bh[nt >> 1][(nt & 1) * 2], bh[nt >> 1][(nt & 1) * 2 + 1]);
                    mma16816(acc[mt][nt], afr[mt],
                             bl[nt >> 1][(nt & 1) * 2], bl[nt >> 1][(nt & 1) * 2 + 1]);
                }
        }
        __syncthreads();
    }

    const float al_ = *alpha_p, be = *beta_p;

    #pragma unroll
    for (int mt = 0; mt < 2; mt++) {
        const size_t r1 = (size_t)by * 128 + wm * 32 + mt * 16 + (lane >> 2);
        const size_t r2 = r1 + 8;
        const float s1 = al_ * g_su[r1], s2 = al_ * g_su[r2];
        #pragma unroll
        for (int nt = 0; nt < 4; nt++) {
            const int c = bx * 64 + wn * 32 + nt * 8 + ((lane & 3) << 1);
            const float sv0 = be * g_sv[c], sv1 = be * g_sv[c + 1];
            const float* d = acc[mt][nt];
            float2 o1 = make_float2(d[0] - s1 - sv0, d[1] - s1 - sv1);
            float2 o2 = make_float2(d[2] - s2 - sv0, d[3] - s2 - sv1);
            *reinterpret_cast<float2*>(&out[r1 * PD + c]) = o1;
            *reinterpret_cast<float2*>(&out[r2 * PD + c]) = o2;
        }
    }
}

// ---------------------------------------------------------------------------
extern "C" void kernel_launch(void* const* d_in, const int* in_sizes, int n_in,
                              void* d_out, int out_size)
{
    const float* x      = (const float*)d_in[0];  // [4096, 1024]
    const float* feats  = (const float*)d_in[1];  // [2048, 1024]
    const float* protos = (const float*)d_in[2];  // [512, 1024]
    const float* alpha  = (const float*)d_in[3];
    const float* beta   = (const float*)d_in[4];
    const float* theta  = (const float*)d_in[5];
    float* out = (float*)d_out;                   // [4096, 512]

    cudaFuncSetAttribute(tv_gemm12, cudaFuncAttributeMaxDynamicSharedMemorySize, SMEM12);
    cudaFuncSetAttribute(tv_gemm3,  cudaFuncAttributeMaxDynamicSharedMemorySize, SMEM3);

    constexpr int NTOT = BD * ID + FD * ID + PD * ID;   // multiple of 2048
    split_all<<<NTOT / 2048, 256>>>(x, feats, protos);

    tv_gemm12<<<576, 256, SMEM12>>>(alpha, beta, theta);
    tv_gemm3<<<dim3(8, 32), 256, SMEM3>>>(out, alpha, beta);
}

// round 14
// speedup vs baseline: 2.2315x; 1.1863x over previous
#include <cuda_runtime.h>
#include <cuda_bf16.h>
#include <cstdint>

#define BD 4096
#define ID 1024
#define PD 512
#define FD 2048
#define K2 4096

#define SMEM12 (3 * 32768)   // 3 stages x (16KB A + 16KB B)
#define SMEM3  (4 * 24576)   // 4 stages x (16KB A-hi + 8KB B-hi)

// ---------------- scratch (device globals; allocation-free) ----------------
__device__ __align__(256) __nv_bfloat16 g_xh[(size_t)BD*ID];
__device__ __align__(256) __nv_bfloat16 g_xl[(size_t)BD*ID];
__device__ __align__(256) __nv_bfloat16 g_fh[(size_t)FD*ID];
__device__ __align__(256) __nv_bfloat16 g_fl[(size_t)FD*ID];
__device__ __align__(256) __nv_bfloat16 g_ph[(size_t)PD*ID];
__device__ __align__(256) __nv_bfloat16 g_pl[(size_t)PD*ID];
__device__ __align__(256) __nv_bfloat16 g_Ah[(size_t)BD*K2];  // [u^2 | u] hi ONLY
__device__ __align__(256) __nv_bfloat16 g_Ch[(size_t)PD*K2];  // [th*v^2+al*v | be*v^2] hi ONLY
__device__ float g_su[BD];   // raw sum_f u^2
__device__ float g_sv[PD];   // raw sum_f v^2

// ---------------- PTX helpers ----------------
__device__ __forceinline__ uint32_t smem_u32(const void* p) {
    uint32_t a;
    asm("{ .reg .u64 t; cvta.to.shared.u64 t, %1; cvt.u32.u64 %0, t; }" : "=r"(a) : "l"(p));
    return a;
}
__device__ __forceinline__ void cp16(uint32_t dst, const void* src) {
    asm volatile("cp.async.cg.shared.global [%0], [%1], 16;" :: "r"(dst), "l"(src));
}
__device__ __forceinline__ void cp_commit() { asm volatile("cp.async.commit_group;" ::: "memory"); }
template<int N> __device__ __forceinline__ void cp_wait() {
    asm volatile("cp.async.wait_group %0;" :: "n"(N) : "memory");
}
__device__ __forceinline__ void ldsm4(uint32_t (&r)[4], uint32_t addr) {
    asm volatile("ldmatrix.sync.aligned.m8n8.x4.shared.b16 {%0,%1,%2,%3}, [%4];"
        : "=r"(r[0]), "=r"(r[1]), "=r"(r[2]), "=r"(r[3]) : "r"(addr));
}
__device__ __forceinline__ void mma16816(float* d, const uint32_t* a, uint32_t b0, uint32_t b1) {
    asm volatile("mma.sync.aligned.m16n8k16.row.col.f32.bf16.bf16.f32 "
        "{%0,%1,%2,%3}, {%4,%5,%6,%7}, {%8,%9}, {%0,%1,%2,%3};"
        : "+f"(d[0]), "+f"(d[1]), "+f"(d[2]), "+f"(d[3])
        : "r"(a[0]), "r"(a[1]), "r"(a[2]), "r"(a[3]), "r"(b0), "r"(b1));
}

// ---------------- vectorized split conversion + accumulator zero ----------
__global__ __launch_bounds__(256) void split_all(const float* __restrict__ x,
                                                 const float* __restrict__ f,
                                                 const float* __restrict__ p)
{
    const int t = blockIdx.x * 256 + threadIdx.x;
    const size_t i = (size_t)t * 8;
    constexpr size_t N1 = (size_t)BD * ID;
    constexpr size_t N2 = N1 + (size_t)FD * ID;
    const float* src; __nv_bfloat16 *hp, *lp; size_t j;
    if (i < N1)      { j = i;      src = x; hp = g_xh; lp = g_xl; }
    else if (i < N2) { j = i - N1; src = f; hp = g_fh; lp = g_fl; }
    else             { j = i - N2; src = p; hp = g_ph; lp = g_pl; }

    float4 v0 = *reinterpret_cast<const float4*>(src + j);
    float4 v1 = *reinterpret_cast<const float4*>(src + j + 4);
    float vv[8] = {v0.x, v0.y, v0.z, v0.w, v1.x, v1.y, v1.z, v1.w};
    __nv_bfloat16 hh[8], ll[8];
    #pragma unroll
    for (int k = 0; k < 8; k++) {
        hh[k] = __float2bfloat16(vv[k]);
        ll[k] = __float2bfloat16(vv[k] - __bfloat162float(hh[k]));
    }
    *reinterpret_cast<uint4*>(hp + j) = *reinterpret_cast<const uint4*>(hh);
    *reinterpret_cast<uint4*>(lp + j) = *reinterpret_cast<const uint4*>(ll);

    if (t < BD) g_su[t] = 0.0f;
    if (t < PD) g_sv[t] = 0.0f;
}

// ---------------------------------------------------------------------------
// Fused GEMM1+GEMM2 (R11-proven loop): 128x128xBK64, 3 sequential split passes.
// bid <  512 : MODE0  x @ f^T -> relu -> g_Ah [u^2|u] (hi only), atomic sum u^2
// bid >= 512 : MODE1  p @ f^T -> relu -> g_Ch (hi only), atomic sum v^2
// ---------------------------------------------------------------------------
__global__ void __launch_bounds__(256, 2)
tv_gemm12(const float* __restrict__ alpha_p,
          const float* __restrict__ beta_p,
          const float* __restrict__ theta_p)
{
    constexpr int K  = ID;
    constexpr int KT = K / 64;
    constexpr int T  = 3 * KT;

    extern __shared__ __align__(1024) char smem[];
    const uint32_t sb = smem_u32(smem);
    const int tid  = threadIdx.x;
    const int lane = tid & 31, wid = tid >> 5;
    const int wm = wid >> 2, wn = wid & 3;          // 2 x 4 warp grid

    const int bid   = blockIdx.x;
    const int mode1 = (bid >= 512);
    const int lbid  = mode1 ? bid - 512 : bid;
    const int bx    = lbid & 15;
    const int by    = lbid >> 4;

    const __nv_bfloat16* Ahi = (mode1 ? g_ph : g_xh) + (size_t)by * 128 * K;
    const __nv_bfloat16* Alo = (mode1 ? g_pl : g_xl) + (size_t)by * 128 * K;
    const __nv_bfloat16* Bhi = g_fh + (size_t)bx * 128 * K;
    const __nv_bfloat16* Blo = g_fl + (size_t)bx * 128 * K;

    float acc[4][4][4];
    #pragma unroll
    for (int a = 0; a < 4; a++)
        #pragma unroll
        for (int b = 0; b < 4; b++)
            #pragma unroll
            for (int c = 0; c < 4; c++) acc[a][b][c] = 0.0f;

    auto load_tiles = [&](int i) {
        const int p  = i / KT;
        const int k0 = (i - p * KT) << 6;
        const __nv_bfloat16* As = (p == 2) ? Alo : Ahi;
        const __nv_bfloat16* Bs = (p == 1) ? Blo : Bhi;
        const uint32_t base = sb + (i % 3) * 32768;
        #pragma unroll
        for (int it = 0; it < 4; it++) {
            const int idx = (it << 8) + tid;          // 0..1023
            const int r = idx >> 3, c = idx & 7;
            const uint32_t sw = (uint32_t)((c ^ (r & 7)) << 4);
            cp16(base + r * 128 + sw,         As + (size_t)r * K + k0 + (c << 3));
            cp16(base + 16384 + r * 128 + sw, Bs + (size_t)r * K + k0 + (c << 3));
        }
    };

    load_tiles(0); cp_commit();
    load_tiles(1); cp_commit();

    for (int i = 0; i < T; i++) {
        if (i + 2 < T)      { load_tiles(i + 2); cp_commit(); cp_wait<2>(); }
        else if (i + 1 < T) { cp_wait<1>(); }
        else                { cp_wait<0>(); }
        __syncthreads();

        const uint32_t Ab = sb + (i % 3) * 32768;
        const uint32_t Bb = Ab + 16384;

        #pragma unroll
        for (int ks = 0; ks < 4; ks++) {
            uint32_t afr[4][4], bfr[2][4];
            #pragma unroll
            for (int mt = 0; mt < 4; mt++) {
                const int r  = wm * 64 + mt * 16 + (lane & 15);
                const int cb = (ks << 1) + (lane >> 4);
                ldsm4(afr[mt], Ab + r * 128 + ((cb ^ (r & 7)) << 4));
            }
            #pragma unroll
            for (int np = 0; np < 2; np++) {
                const int g  = lane >> 3;
                const int r  = wn * 32 + np * 16 + ((g & 2) << 2) + (lane & 7);
                const int cb = (ks << 1) + (g & 1);
                ldsm4(bfr[np], Bb + r * 128 + ((cb ^ (r & 7)) << 4));
            }
            #pragma unroll
            for (int mt = 0; mt < 4; mt++)
                #pragma unroll
                for (int nt = 0; nt < 4; nt++)
                    mma16816(acc[mt][nt], afr[mt],
                             bfr[nt >> 1][(nt & 1) * 2], bfr[nt >> 1][(nt & 1) * 2 + 1]);
        }
        __syncthreads();
    }

    // ---------------- epilogue: hi-only stores + fused row-sum atomics -----
    float al_ = 0.f, be = 0.f, th = 0.f;
    if (mode1) { al_ = *alpha_p; be = *beta_p; th = *theta_p; }

    float rs[4][2];
    #pragma unroll
    for (int mt = 0; mt < 4; mt++) { rs[mt][0] = 0.0f; rs[mt][1] = 0.0f; }

    #pragma unroll
    for (int mt = 0; mt < 4; mt++) {
        const size_t rbase = (size_t)by * 128 + wm * 64 + mt * 16 + (lane >> 2);
        #pragma unroll
        for (int nt = 0; nt < 4; nt++) {
            const int c = bx * 128 + wn * 32 + nt * 8 + ((lane & 3) << 1);
            #pragma unroll
            for (int h = 0; h < 2; h++) {
                const float v0 = fmaxf(acc[mt][nt][h * 2 + 0], 0.0f);
                const float v1 = fmaxf(acc[mt][nt][h * 2 + 1], 0.0f);
                const float q0 = v0 * v0, q1 = v1 * v1;
                rs[mt][h] += q0 + q1;
                const size_t rb = (rbase + h * 8) * (size_t)K2;
                __nv_bfloat162 hh;
                if (!mode1) {
                    hh.x = __float2bfloat16(q0); hh.y = __float2bfloat16(q1);
                    *reinterpret_cast<__nv_bfloat162*>(&g_Ah[rb + c]) = hh;
                    hh.x = __float2bfloat16(v0); hh.y = __float2bfloat16(v1);
                    *reinterpret_cast<__nv_bfloat162*>(&g_Ah[rb + FD + c]) = hh;
                } else {
                    hh.x = __float2bfloat16(fmaf(th, q0, al_ * v0));
                    hh.y = __float2bfloat16(fmaf(th, q1, al_ * v1));
                    *reinterpret_cast<__nv_bfloat162*>(&g_Ch[rb + c]) = hh;
                    hh.x = __float2bfloat16(be * q0);
                    hh.y = __float2bfloat16(be * q1);
                    *reinterpret_cast<__nv_bfloat162*>(&g_Ch[rb + FD + c]) = hh;
                }
            }
        }
    }

    float* sums = mode1 ? g_sv : g_su;
    #pragma unroll
    for (int mt = 0; mt < 4; mt++)
        #pragma unroll
        for (int h = 0; h < 2; h++) {
            float v = rs[mt][h];
            v += __shfl_xor_sync(0xffffffffu, v, 1);
            v += __shfl_xor_sync(0xffffffffu, v, 2);
            if ((lane & 3) == 0) {
                const int row = by * 128 + wm * 64 + mt * 16 + (lane >> 2) + h * 8;
                atomicAdd(&sums[row], v);
            }
        }
}

// ---------------------------------------------------------------------------
// GEMM3 (pure bf16 single-pass): 128(M) x 64(N), K=4096, BK=64, 4-stage.
// out = acc - alpha*su[row] - beta*sv[col]
// ---------------------------------------------------------------------------
__global__ void __launch_bounds__(256, 2)
tv_gemm3(float* __restrict__ out,
         const float* __restrict__ alpha_p,
         const float* __restrict__ beta_p)
{
    constexpr int K = K2;
    constexpr int T = K / 64;          // 64 chunks

    extern __shared__ __align__(1024) char smem[];
    const uint32_t sb = smem_u32(smem);
    const int tid  = threadIdx.x;
    const int lane = tid & 31, wid = tid >> 5;
    const int wm = wid >> 1, wn = wid & 1;          // 4 x 2 warp grid (32x32 warp tile)

    const int bx = blockIdx.x;                      // 8 N-tiles
    const int by = blockIdx.y;                      // 32 M-tiles

    const __nv_bfloat16* Ahi = g_Ah + (size_t)by * 128 * K;
    const __nv_bfloat16* Bhi = g_Ch + (size_t)bx * 64 * K;

    float acc[2][4][4];
    #pragma unroll
    for (int a = 0; a < 2; a++)
        #pragma unroll
        for (int b = 0; b < 4; b++)
            #pragma unroll
            for (int c = 0; c < 4; c++) acc[a][b][c] = 0.0f;

    // stage: [A-hi 128x128B | B-hi 64x128B] = 24KB
    auto load_tiles = [&](int i) {
        const int k0 = i << 6;
        const uint32_t base = sb + (i & 3) * 24576;
        #pragma unroll
        for (int it = 0; it < 4; it++) {            // A: 1024 chunk-slots
            const int idx = (it << 8) + tid;
            const int r = idx >> 3, c = idx & 7;
            const uint32_t sw = (uint32_t)((c ^ (r & 7)) << 4);
            cp16(base + r * 128 + sw, Ahi + (size_t)r * K + k0 + (c << 3));
        }
        #pragma unroll
        for (int it = 0; it < 2; it++) {            // B: 512 chunk-slots
            const int idx = (it << 8) + tid;
            const int r = idx >> 3, c = idx & 7;
            const uint32_t sw = (uint32_t)((c ^ (r & 7)) << 4);
            cp16(base + 16384 + r * 128 + sw, Bhi + (size_t)r * K + k0 + (c << 3));
        }
    };

    load_tiles(0); cp_commit();
    load_tiles(1); cp_commit();
    load_tiles(2); cp_commit();

    for (int i = 0; i < T; i++) {
        if (i + 3 < T)      { load_tiles(i + 3); cp_commit(); cp_wait<3>(); }
        else if (i + 2 < T) { cp_wait<2>(); }
        else if (i + 1 < T) { cp_wait<1>(); }
        else                { cp_wait<0>(); }
        __syncthreads();

        const uint32_t Ab = sb + (i & 3) * 24576;
        const uint32_t Bb = Ab + 16384;

        #pragma unroll
        for (int ks = 0; ks < 4; ks++) {
            uint32_t afr[2][4], bfr[2][4];
            #pragma unroll
            for (int mt = 0; mt < 2; mt++) {
                const int r  = wm * 32 + mt * 16 + (lane & 15);
                const int cb = (ks << 1) + (lane >> 4);
                ldsm4(afr[mt], Ab + r * 128 + ((cb ^ (r & 7)) << 4));
            }
            #pragma unroll
            for (int np = 0; np < 2; np++) {
                const int g  = lane >> 3;
                const int r  = wn * 32 + np * 16 + ((g & 2) << 2) + (lane & 7);
                const int cb = (ks << 1) + (g & 1);
                ldsm4(bfr[np], Bb + r * 128 + ((cb ^ (r & 7)) << 4));
            }
            #pragma unroll
            for (int mt = 0; mt < 2; mt++)
                #pragma unroll
                for (int nt = 0; nt < 4; nt++)
                    mma16816(acc[mt][nt], afr[mt],
                             bfr[nt >> 1][(nt & 1) * 2], bfr[nt >> 1][(nt & 1) * 2 + 1]);
        }
        __syncthreads();
    }

    const float al_ = *alpha_p, be = *beta_p;

    #pragma unroll
    for (int mt = 0; mt < 2; mt++) {
        const size_t r1 = (size_t)by * 128 + wm * 32 + mt * 16 + (lane >> 2);
        const size_t r2 = r1 + 8;
        const float s1 = al_ * g_su[r1], s2 = al_ * g_su[r2];
        #pragma unroll
        for (int nt = 0; nt < 4; nt++) {
            const int c = bx * 64 + wn * 32 + nt * 8 + ((lane & 3) << 1);
            const float sv0 = be * g_sv[c], sv1 = be * g_sv[c + 1];
            const float* d = acc[mt][nt];
            float2 o1 = make_float2(d[0] - s1 - sv0, d[1] - s1 - sv1);
            float2 o2 = make_float2(d[2] - s2 - sv0, d[3] - s2 - sv1);
            *reinterpret_cast<float2*>(&out[r1 * PD + c]) = o1;
            *reinterpret_cast<float2*>(&out[r2 * PD + c]) = o2;
        }
    }
}

// ---------------------------------------------------------------------------
extern "C" void kernel_launch(void* const* d_in, const int* in_sizes, int n_in,
                              void* d_out, int out_size)
{
    const float* x      = (const float*)d_in[0];  // [4096, 1024]
    const float* feats  = (const float*)d_in[1];  // [2048, 1024]
    const float* protos = (const float*)d_in[2];  // [512, 1024]
    const float* alpha  = (const float*)d_in[3];
    const float* beta   = (const float*)d_in[4];
    const float* theta  = (const float*)d_in[5];
    float* out = (float*)d_out;                   // [4096, 512]

    cudaFuncSetAttribute(tv_gemm12, cudaFuncAttributeMaxDynamicSharedMemorySize, SMEM12);
    cudaFuncSetAttribute(tv_gemm3,  cudaFuncAttributeMaxDynamicSharedMemorySize, SMEM3);

    constexpr int NTOT = BD * ID + FD * ID + PD * ID;   // multiple of 2048
    split_all<<<NTOT / 2048, 256>>>(x, feats, protos);

    tv_gemm12<<<576, 256, SMEM12>>>(alpha, beta, theta);
    tv_gemm3<<<dim3(8, 32), 256, SMEM3>>>(out, alpha, beta);
}

// round 15
// speedup vs baseline: 2.8783x; 1.2898x over previous
#include <cuda_runtime.h>
#include <cuda_bf16.h>
#include <cstdint>

#define BD 4096
#define ID 1024
#define PD 512
#define FD 2048
#define K2 4096

#define SMEM12 (3 * 32768)   // 3 stages x (16KB A + 16KB B)
#define SMEM3  (4 * 24576)   // 4 stages x (16KB A-hi + 8KB B-hi)

// ---------------- scratch (device globals; allocation-free) ----------------
__device__ __align__(256) __nv_bfloat16 g_xh[(size_t)BD*ID];
__device__ __align__(256) __nv_bfloat16 g_fh[(size_t)FD*ID];
__device__ __align__(256) __nv_bfloat16 g_fl[(size_t)FD*ID];
__device__ __align__(256) __nv_bfloat16 g_ph[(size_t)PD*ID];
__device__ __align__(256) __nv_bfloat16 g_Ah[(size_t)BD*K2];  // [u^2 | u] hi ONLY
__device__ __align__(256) __nv_bfloat16 g_Ch[(size_t)PD*K2];  // [th*v^2+al*v | be*v^2] hi ONLY
__device__ float g_su[BD];   // raw sum_f u^2
__device__ float g_sv[PD];   // raw sum_f v^2

// ---------------- PTX helpers ----------------
__device__ __forceinline__ uint32_t smem_u32(const void* p) {
    uint32_t a;
    asm("{ .reg .u64 t; cvta.to.shared.u64 t, %1; cvt.u32.u64 %0, t; }" : "=r"(a) : "l"(p));
    return a;
}
__device__ __forceinline__ void cp16(uint32_t dst, const void* src) {
    asm volatile("cp.async.cg.shared.global [%0], [%1], 16;" :: "r"(dst), "l"(src));
}
__device__ __forceinline__ void cp_commit() { asm volatile("cp.async.commit_group;" ::: "memory"); }
template<int N> __device__ __forceinline__ void cp_wait() {
    asm volatile("cp.async.wait_group %0;" :: "n"(N) : "memory");
}
__device__ __forceinline__ void ldsm4(uint32_t (&r)[4], uint32_t addr) {
    asm volatile("ldmatrix.sync.aligned.m8n8.x4.shared.b16 {%0,%1,%2,%3}, [%4];"
        : "=r"(r[0]), "=r"(r[1]), "=r"(r[2]), "=r"(r[3]) : "r"(addr));
}
__device__ __forceinline__ void mma16816(float* d, const uint32_t* a, uint32_t b0, uint32_t b1) {
    asm volatile("mma.sync.aligned.m16n8k16.row.col.f32.bf16.bf16.f32 "
        "{%0,%1,%2,%3}, {%4,%5,%6,%7}, {%8,%9}, {%0,%1,%2,%3};"
        : "+f"(d[0]), "+f"(d[1]), "+f"(d[2]), "+f"(d[3])
        : "r"(a[0]), "r"(a[1]), "r"(a[2]), "r"(a[3]), "r"(b0), "r"(b1));
}

// ---------------- vectorized split conversion + accumulator zero ----------
// x, protos: hi only (their residual pass was dropped). features: hi + lo.
__global__ __launch_bounds__(256) void split_all(const float* __restrict__ x,
                                                 const float* __restrict__ f,
                                                 const float* __restrict__ p)
{
    const int t = blockIdx.x * 256 + threadIdx.x;
    const size_t i = (size_t)t * 8;
    constexpr size_t N1 = (size_t)BD * ID;
    constexpr size_t N2 = N1 + (size_t)FD * ID;
    const float* src; __nv_bfloat16 *hp, *lp; size_t j;
    if (i < N1)      { j = i;      src = x; hp = g_xh; lp = nullptr; }
    else if (i < N2) { j = i - N1; src = f; hp = g_fh; lp = g_fl;    }
    else             { j = i - N2; src = p; hp = g_ph; lp = nullptr; }

    float4 v0 = *reinterpret_cast<const float4*>(src + j);
    float4 v1 = *reinterpret_cast<const float4*>(src + j + 4);
    float vv[8] = {v0.x, v0.y, v0.z, v0.w, v1.x, v1.y, v1.z, v1.w};
    __nv_bfloat16 hh[8], ll[8];
    #pragma unroll
    for (int k = 0; k < 8; k++) {
        hh[k] = __float2bfloat16(vv[k]);
        ll[k] = __float2bfloat16(vv[k] - __bfloat162float(hh[k]));
    }
    *reinterpret_cast<uint4*>(hp + j) = *reinterpret_cast<const uint4*>(hh);
    if (lp) *reinterpret_cast<uint4*>(lp + j) = *reinterpret_cast<const uint4*>(ll);

    if (t < BD) g_su[t] = 0.0f;
    if (t < PD) g_sv[t] = 0.0f;
}

// ---------------------------------------------------------------------------
// Fused GEMM1+GEMM2: 128x128xBK64, TWO sequential passes (Ah*Bh, Ah*Bl).
// bid <  512 : MODE0  x @ f^T -> relu -> g_Ah [u^2|u] (hi only), atomic sum u^2
// bid >= 512 : MODE1  p @ f^T -> relu -> g_Ch (hi only), atomic sum v^2
// ---------------------------------------------------------------------------
__global__ void __launch_bounds__(256, 2)
tv_gemm12(const float* __restrict__ alpha_p,
          const float* __restrict__ beta_p,
          const float* __restrict__ theta_p)
{
    constexpr int K  = ID;
    constexpr int KT = K / 64;
    constexpr int T  = 2 * KT;         // 2 passes x 16 chunks

    extern __shared__ __align__(1024) char smem[];
    const uint32_t sb = smem_u32(smem);
    const int tid  = threadIdx.x;
    const int lane = tid & 31, wid = tid >> 5;
    const int wm = wid >> 2, wn = wid & 3;          // 2 x 4 warp grid

    const int bid   = blockIdx.x;
    const int mode1 = (bid >= 512);
    const int lbid  = mode1 ? bid - 512 : bid;
    const int bx    = lbid & 15;
    const int by    = lbid >> 4;

    const __nv_bfloat16* Ahi = (mode1 ? g_ph : g_xh) + (size_t)by * 128 * K;
    const __nv_bfloat16* Bhi = g_fh + (size_t)bx * 128 * K;
    const __nv_bfloat16* Blo = g_fl + (size_t)bx * 128 * K;

    float acc[4][4][4];
    #pragma unroll
    for (int a = 0; a < 4; a++)
        #pragma unroll
        for (int b = 0; b < 4; b++)
            #pragma unroll
            for (int c = 0; c < 4; c++) acc[a][b][c] = 0.0f;

    auto load_tiles = [&](int i) {
        const int p  = i / KT;
        const int k0 = (i - p * KT) << 6;
        const __nv_bfloat16* Bs = (p == 1) ? Blo : Bhi;
        const uint32_t base = sb + (i % 3) * 32768;
        #pragma unroll
        for (int it = 0; it < 4; it++) {
            const int idx = (it << 8) + tid;          // 0..1023
            const int r = idx >> 3, c = idx & 7;
            const uint32_t sw = (uint32_t)((c ^ (r & 7)) << 4);
            cp16(base + r * 128 + sw,         Ahi + (size_t)r * K + k0 + (c << 3));
            cp16(base + 16384 + r * 128 + sw, Bs  + (size_t)r * K + k0 + (c << 3));
        }
    };

    load_tiles(0); cp_commit();
    load_tiles(1); cp_commit();

    for (int i = 0; i < T; i++) {
        if (i + 2 < T)      { load_tiles(i + 2); cp_commit(); cp_wait<2>(); }
        else if (i + 1 < T) { cp_wait<1>(); }
        else                { cp_wait<0>(); }
        __syncthreads();

        const uint32_t Ab = sb + (i % 3) * 32768;
        const uint32_t Bb = Ab + 16384;

        #pragma unroll
        for (int ks = 0; ks < 4; ks++) {
            uint32_t afr[4][4], bfr[2][4];
            #pragma unroll
            for (int mt = 0; mt < 4; mt++) {
                const int r  = wm * 64 + mt * 16 + (lane & 15);
                const int cb = (ks << 1) + (lane >> 4);
                ldsm4(afr[mt], Ab + r * 128 + ((cb ^ (r & 7)) << 4));
            }
            #pragma unroll
            for (int np = 0; np < 2; np++) {
                const int g  = lane >> 3;
                const int r  = wn * 32 + np * 16 + ((g & 2) << 2) + (lane & 7);
                const int cb = (ks << 1) + (g & 1);
                ldsm4(bfr[np], Bb + r * 128 + ((cb ^ (r & 7)) << 4));
            }
            #pragma unroll
            for (int mt = 0; mt < 4; mt++)
                #pragma unroll
                for (int nt = 0; nt < 4; nt++)
                    mma16816(acc[mt][nt], afr[mt],
                             bfr[nt >> 1][(nt & 1) * 2], bfr[nt >> 1][(nt & 1) * 2 + 1]);
        }
        __syncthreads();
    }

    // ---------------- epilogue: hi-only stores + fused row-sum atomics -----
    float al_ = 0.f, be = 0.f, th = 0.f;
    if (mode1) { al_ = *alpha_p; be = *beta_p; th = *theta_p; }

    float rs[4][2];
    #pragma unroll
    for (int mt = 0; mt < 4; mt++) { rs[mt][0] = 0.0f; rs[mt][1] = 0.0f; }

    #pragma unroll
    for (int mt = 0; mt < 4; mt++) {
        const size_t rbase = (size_t)by * 128 + wm * 64 + mt * 16 + (lane >> 2);
        #pragma unroll
        for (int nt = 0; nt < 4; nt++) {
            const int c = bx * 128 + wn * 32 + nt * 8 + ((lane & 3) << 1);
            #pragma unroll
            for (int h = 0; h < 2; h++) {
                const float v0 = fmaxf(acc[mt][nt][h * 2 + 0], 0.0f);
                const float v1 = fmaxf(acc[mt][nt][h * 2 + 1], 0.0f);
                const float q0 = v0 * v0, q1 = v1 * v1;
                rs[mt][h] += q0 + q1;
                const size_t rb = (rbase + h * 8) * (size_t)K2;
                __nv_bfloat162 hh;
                if (!mode1) {
                    hh.x = __float2bfloat16(q0); hh.y = __float2bfloat16(q1);
                    *reinterpret_cast<__nv_bfloat162*>(&g_Ah[rb + c]) = hh;
                    hh.x = __float2bfloat16(v0); hh.y = __float2bfloat16(v1);
                    *reinterpret_cast<__nv_bfloat162*>(&g_Ah[rb + FD + c]) = hh;
                } else {
                    hh.x = __float2bfloat16(fmaf(th, q0, al_ * v0));
                    hh.y = __float2bfloat16(fmaf(th, q1, al_ * v1));
                    *reinterpret_cast<__nv_bfloat162*>(&g_Ch[rb + c]) = hh;
                    hh.x = __float2bfloat16(be * q0);
                    hh.y = __float2bfloat16(be * q1);
                    *reinterpret_cast<__nv_bfloat162*>(&g_Ch[rb + FD + c]) = hh;
                }
            }
        }
    }

    float* sums = mode1 ? g_sv : g_su;
    #pragma unroll
    for (int mt = 0; mt < 4; mt++)
        #pragma unroll
        for (int h = 0; h < 2; h++) {
            float v = rs[mt][h];
            v += __shfl_xor_sync(0xffffffffu, v, 1);
            v += __shfl_xor_sync(0xffffffffu, v, 2);
            if ((lane & 3) == 0) {
                const int row = by * 128 + wm * 64 + mt * 16 + (lane >> 2) + h * 8;
                atomicAdd(&sums[row], v);
            }
        }
}

// ---------------------------------------------------------------------------
// GEMM3 (pure bf16 single-pass, R14-proven): 128(M) x 64(N), K=4096, BK=64,
// 4-stage. out = acc - alpha*su[row] - beta*sv[col]
// ---------------------------------------------------------------------------
__global__ void __launch_bounds__(256, 2)
tv_gemm3(float* __restrict__ out,
         const float* __restrict__ alpha_p,
         const float* __restrict__ beta_p)
{
    constexpr int K = K2;
    constexpr int T = K / 64;          // 64 chunks

    extern __shared__ __align__(1024) char smem[];
    const uint32_t sb = smem_u32(smem);
    const int tid  = threadIdx.x;
    const int lane = tid & 31, wid = tid >> 5;
    const int wm = wid >> 1, wn = wid & 1;          // 4 x 2 warp grid (32x32 warp tile)

    const int bx = blockIdx.x;                      // 8 N-tiles
    const int by = blockIdx.y;                      // 32 M-tiles

    const __nv_bfloat16* Ahi = g_Ah + (size_t)by * 128 * K;
    const __nv_bfloat16* Bhi = g_Ch + (size_t)bx * 64 * K;

    float acc[2][4][4];
    #pragma unroll
    for (int a = 0; a < 2; a++)
        #pragma unroll
        for (int b = 0; b < 4; b++)
            #pragma unroll
            for (int c = 0; c < 4; c++) acc[a][b][c] = 0.0f;

    // stage: [A-hi 128x128B | B-hi 64x128B] = 24KB
    auto load_tiles = [&](int i) {
        const int k0 = i << 6;
        const uint32_t base = sb + (i & 3) * 24576;
        #pragma unroll
        for (int it = 0; it < 4; it++) {            // A: 1024 chunk-slots
            const int idx = (it << 8) + tid;
            const int r = idx >> 3, c = idx & 7;
            const uint32_t sw = (uint32_t)((c ^ (r & 7)) << 4);
            cp16(base + r * 128 + sw, Ahi + (size_t)r * K + k0 + (c << 3));
        }
        #pragma unroll
        for (int it = 0; it < 2; it++) {            // B: 512 chunk-slots
            const int idx = (it << 8) + tid;
            const int r = idx >> 3, c = idx & 7;
            const uint32_t sw = (uint32_t)((c ^ (r & 7)) << 4);
            cp16(base + 16384 + r * 128 + sw, Bhi + (size_t)r * K + k0 + (c << 3));
        }
    };

    load_tiles(0); cp_commit();
    load_tiles(1); cp_commit();
    load_tiles(2); cp_commit();

    for (int i = 0; i < T; i++) {
        if (i + 3 < T)      { load_tiles(i + 3); cp_commit(); cp_wait<3>(); }
        else if (i + 2 < T) { cp_wait<2>(); }
        else if (i + 1 < T) { cp_wait<1>(); }
        else                { cp_wait<0>(); }
        __syncthreads();

        const uint32_t Ab = sb + (i & 3) * 24576;
        const uint32_t Bb = Ab + 16384;

        #pragma unroll
        for (int ks = 0; ks < 4; ks++) {
            uint32_t afr[2][4], bfr[2][4];
            #pragma unroll
            for (int mt = 0; mt < 2; mt++) {
                const int r  = wm * 32 + mt * 16 + (lane & 15);
                const int cb = (ks << 1) + (lane >> 4);
                ldsm4(afr[mt], Ab + r * 128 + ((cb ^ (r & 7)) << 4));
            }
            #pragma unroll
            for (int np = 0; np < 2; np++) {
                const int g  = lane >> 3;
                const int r  = wn * 32 + np * 16 + ((g & 2) << 2) + (lane & 7);
                const int cb = (ks << 1) + (g & 1);
                ldsm4(bfr[np], Bb + r * 128 + ((cb ^ (r & 7)) << 4));
            }
            #pragma unroll
            for (int mt = 0; mt < 2; mt++)
                #pragma unroll
                for (int nt = 0; nt < 4; nt++)
                    mma16816(acc[mt][nt], afr[mt],
                             bfr[nt >> 1][(nt & 1) * 2], bfr[nt >> 1][(nt & 1) * 2 + 1]);
        }
        __syncthreads();
    }

    const float al_ = *alpha_p, be = *beta_p;

    #pragma unroll
    for (int mt = 0; mt < 2; mt++) {
        const size_t r1 = (size_t)by * 128 + wm * 32 + mt * 16 + (lane >> 2);
        const size_t r2 = r1 + 8;
        const float s1 = al_ * g_su[r1], s2 = al_ * g_su[r2];
        #pragma unroll
        for (int nt = 0; nt < 4; nt++) {
            const int c = bx * 64 + wn * 32 + nt * 8 + ((lane & 3) << 1);
            const float sv0 = be * g_sv[c], sv1 = be * g_sv[c + 1];
            const float* d = acc[mt][nt];
            float2 o1 = make_float2(d[0] - s1 - sv0, d[1] - s1 - sv1);
            float2 o2 = make_float2(d[2] - s2 - sv0, d[3] - s2 - sv1);
            *reinterpret_cast<float2*>(&out[r1 * PD + c]) = o1;
            *reinterpret_cast<float2*>(&out[r2 * PD + c]) = o2;
        }
    }
}

// ---------------------------------------------------------------------------
extern "C" void kernel_launch(void* const* d_in, const int* in_sizes, int n_in,
                              void* d_out, int out_size)
{
    const float* x      = (const float*)d_in[0];  // [4096, 1024]
    const float* feats  = (const float*)d_in[1];  // [2048, 1024]
    const float* protos = (const float*)d_in[2];  // [512, 1024]
    const float* alpha  = (const float*)d_in[3];
    const float* beta   = (const float*)d_in[4];
    const float* theta  = (const float*)d_in[5];
    float* out = (float*)d_out;                   // [4096, 512]

    cudaFuncSetAttribute(tv_gemm12, cudaFuncAttributeMaxDynamicSharedMemorySize, SMEM12);
    cudaFuncSetAttribute(tv_gemm3,  cudaFuncAttributeMaxDynamicSharedMemorySize, SMEM3);

    constexpr int NTOT = BD * ID + FD * ID + PD * ID;   // multiple of 2048
    split_all<<<NTOT / 2048, 256>>>(x, feats, protos);

    tv_gemm12<<<576, 256, SMEM12>>>(alpha, beta, theta);
    tv_gemm3<<<dim3(8, 32), 256, SMEM3>>>(out, alpha, beta);
}

// round 16
// speedup vs baseline: 3.9456x; 1.3708x over previous
#include <cuda_runtime.h>
#include <cuda_bf16.h>
#include <cstdint>

#define BD 4096
#define ID 1024
#define PD 512
#define FD 2048
#define K2 4096

#define SMEM12 (3 * 32768)   // 3 stages x (16KB A + 16KB B)
#define SMEM3  (4 * 24576)   // 4 stages x (16KB A-hi + 8KB B-hi)

// ---------------- scratch (device globals; allocation-free) ----------------
__device__ __align__(256) __nv_bfloat16 g_xh[(size_t)BD*ID];
__device__ __align__(256) __nv_bfloat16 g_fh[(size_t)FD*ID];
__device__ __align__(256) __nv_bfloat16 g_ph[(size_t)PD*ID];
__device__ __align__(256) __nv_bfloat16 g_Ah[(size_t)BD*K2];  // [u^2 | u]
__device__ __align__(256) __nv_bfloat16 g_Ch[(size_t)PD*K2];  // [th*v^2+al*v | be*v^2]
__device__ float g_su[BD];   // raw sum_f u^2
__device__ float g_sv[PD];   // raw sum_f v^2

// ---------------- PTX helpers ----------------
__device__ __forceinline__ uint32_t smem_u32(const void* p) {
    uint32_t a;
    asm("{ .reg .u64 t; cvta.to.shared.u64 t, %1; cvt.u32.u64 %0, t; }" : "=r"(a) : "l"(p));
    return a;
}
__device__ __forceinline__ void cp16(uint32_t dst, const void* src) {
    asm volatile("cp.async.cg.shared.global [%0], [%1], 16;" :: "r"(dst), "l"(src));
}
__device__ __forceinline__ void cp_commit() { asm volatile("cp.async.commit_group;" ::: "memory"); }
template<int N> __device__ __forceinline__ void cp_wait() {
    asm volatile("cp.async.wait_group %0;" :: "n"(N) : "memory");
}
__device__ __forceinline__ void ldsm4(uint32_t (&r)[4], uint32_t addr) {
    asm volatile("ldmatrix.sync.aligned.m8n8.x4.shared.b16 {%0,%1,%2,%3}, [%4];"
        : "=r"(r[0]), "=r"(r[1]), "=r"(r[2]), "=r"(r[3]) : "r"(addr));
}
__device__ __forceinline__ void mma16816(float* d, const uint32_t* a, uint32_t b0, uint32_t b1) {
    asm volatile("mma.sync.aligned.m16n8k16.row.col.f32.bf16.bf16.f32 "
        "{%0,%1,%2,%3}, {%4,%5,%6,%7}, {%8,%9}, {%0,%1,%2,%3};"
        : "+f"(d[0]), "+f"(d[1]), "+f"(d[2]), "+f"(d[3])
        : "r"(a[0]), "r"(a[1]), "r"(a[2]), "r"(a[3]), "r"(b0), "r"(b1));
}

// ---------------- vectorized bf16 conversion + accumulator zero ----------
__global__ __launch_bounds__(256) void split_all(const float* __restrict__ x,
                                                 const float* __restrict__ f,
                                                 const float* __restrict__ p)
{
    const int t = blockIdx.x * 256 + threadIdx.x;
    const size_t i = (size_t)t * 8;
    constexpr size_t N1 = (size_t)BD * ID;
    constexpr size_t N2 = N1 + (size_t)FD * ID;
    const float* src; __nv_bfloat16* hp; size_t j;
    if (i < N1)      { j = i;      src = x; hp = g_xh; }
    else if (i < N2) { j = i - N1; src = f; hp = g_fh; }
    else             { j = i - N2; src = p; hp = g_ph; }

    float4 v0 = *reinterpret_cast<const float4*>(src + j);
    float4 v1 = *reinterpret_cast<const float4*>(src + j + 4);
    float vv[8] = {v0.x, v0.y, v0.z, v0.w, v1.x, v1.y, v1.z, v1.w};
    __nv_bfloat16 hh[8];
    #pragma unroll
    for (int k = 0; k < 8; k++) hh[k] = __float2bfloat16(vv[k]);
    *reinterpret_cast<uint4*>(hp + j) = *reinterpret_cast<const uint4*>(hh);

    if (t < BD) g_su[t] = 0.0f;
    if (t < PD) g_sv[t] = 0.0f;
}

// ---------------------------------------------------------------------------
// Fused GEMM1+GEMM2: 128x128xBK64, SINGLE pure-bf16 pass, K=1024 (16 chunks).
// bid <  512 : MODE0  x @ f^T -> relu -> g_Ah [u^2|u], atomic sum u^2
// bid >= 512 : MODE1  p @ f^T -> relu -> g_Ch, atomic sum v^2
// ---------------------------------------------------------------------------
__global__ void __launch_bounds__(256, 2)
tv_gemm12(const float* __restrict__ alpha_p,
          const float* __restrict__ beta_p,
          const float* __restrict__ theta_p)
{
    constexpr int K = ID;
    constexpr int T = K / 64;          // 16 chunks

    extern __shared__ __align__(1024) char smem[];
    const uint32_t sb = smem_u32(smem);
    const int tid  = threadIdx.x;
    const int lane = tid & 31, wid = tid >> 5;
    const int wm = wid >> 2, wn = wid & 3;          // 2 x 4 warp grid

    const int bid   = blockIdx.x;
    const int mode1 = (bid >= 512);
    const int lbid  = mode1 ? bid - 512 : bid;
    const int bx    = lbid & 15;
    const int by    = lbid >> 4;

    const __nv_bfloat16* Ahi = (mode1 ? g_ph : g_xh) + (size_t)by * 128 * K;
    const __nv_bfloat16* Bhi = g_fh + (size_t)bx * 128 * K;

    float acc[4][4][4];
    #pragma unroll
    for (int a = 0; a < 4; a++)
        #pragma unroll
        for (int b = 0; b < 4; b++)
            #pragma unroll
            for (int c = 0; c < 4; c++) acc[a][b][c] = 0.0f;

    auto load_tiles = [&](int i) {
        const int k0 = i << 6;
        const uint32_t base = sb + (i % 3) * 32768;
        #pragma unroll
        for (int it = 0; it < 4; it++) {
            const int idx = (it << 8) + tid;          // 0..1023
            const int r = idx >> 3, c = idx & 7;
            const uint32_t sw = (uint32_t)((c ^ (r & 7)) << 4);
            cp16(base + r * 128 + sw,         Ahi + (size_t)r * K + k0 + (c << 3));
            cp16(base + 16384 + r * 128 + sw, Bhi + (size_t)r * K + k0 + (c << 3));
        }
    };

    load_tiles(0); cp_commit();
    load_tiles(1); cp_commit();

    for (int i = 0; i < T; i++) {
        if (i + 2 < T)      { load_tiles(i + 2); cp_commit(); cp_wait<2>(); }
        else if (i + 1 < T) { cp_wait<1>(); }
        else                { cp_wait<0>(); }
        __syncthreads();

        const uint32_t Ab = sb + (i % 3) * 32768;
        const uint32_t Bb = Ab + 16384;

        #pragma unroll
        for (int ks = 0; ks < 4; ks++) {
            uint32_t afr[4][4], bfr[2][4];
            #pragma unroll
            for (int mt = 0; mt < 4; mt++) {
                const int r  = wm * 64 + mt * 16 + (lane & 15);
                const int cb = (ks << 1) + (lane >> 4);
                ldsm4(afr[mt], Ab + r * 128 + ((cb ^ (r & 7)) << 4));
            }
            #pragma unroll
            for (int np = 0; np < 2; np++) {
                const int g  = lane >> 3;
                const int r  = wn * 32 + np * 16 + ((g & 2) << 2) + (lane & 7);
                const int cb = (ks << 1) + (g & 1);
                ldsm4(bfr[np], Bb + r * 128 + ((cb ^ (r & 7)) << 4));
            }
            #pragma unroll
            for (int mt = 0; mt < 4; mt++)
                #pragma unroll
                for (int nt = 0; nt < 4; nt++)
                    mma16816(acc[mt][nt], afr[mt],
                             bfr[nt >> 1][(nt & 1) * 2], bfr[nt >> 1][(nt & 1) * 2 + 1]);
        }
        __syncthreads();
    }

    // ---------------- epilogue: stores + fused row-sum atomics -------------
    float al_ = 0.f, be = 0.f, th = 0.f;
    if (mode1) { al_ = *alpha_p; be = *beta_p; th = *theta_p; }

    float rs[4][2];
    #pragma unroll
    for (int mt = 0; mt < 4; mt++) { rs[mt][0] = 0.0f; rs[mt][1] = 0.0f; }

    #pragma unroll
    for (int mt = 0; mt < 4; mt++) {
        const size_t rbase = (size_t)by * 128 + wm * 64 + mt * 16 + (lane >> 2);
        #pragma unroll
        for (int nt = 0; nt < 4; nt++) {
            const int c = bx * 128 + wn * 32 + nt * 8 + ((lane & 3) << 1);
            #pragma unroll
            for (int h = 0; h < 2; h++) {
                const float v0 = fmaxf(acc[mt][nt][h * 2 + 0], 0.0f);
                const float v1 = fmaxf(acc[mt][nt][h * 2 + 1], 0.0f);
                const float q0 = v0 * v0, q1 = v1 * v1;
                rs[mt][h] += q0 + q1;
                const size_t rb = (rbase + h * 8) * (size_t)K2;
                __nv_bfloat162 hh;
                if (!mode1) {
                    hh.x = __float2bfloat16(q0); hh.y = __float2bfloat16(q1);
                    *reinterpret_cast<__nv_bfloat162*>(&g_Ah[rb + c]) = hh;
                    hh.x = __float2bfloat16(v0); hh.y = __float2bfloat16(v1);
                    *reinterpret_cast<__nv_bfloat162*>(&g_Ah[rb + FD + c]) = hh;
                } else {
                    hh.x = __float2bfloat16(fmaf(th, q0, al_ * v0));
                    hh.y = __float2bfloat16(fmaf(th, q1, al_ * v1));
                    *reinterpret_cast<__nv_bfloat162*>(&g_Ch[rb + c]) = hh;
                    hh.x = __float2bfloat16(be * q0);
                    hh.y = __float2bfloat16(be * q1);
                    *reinterpret_cast<__nv_bfloat162*>(&g_Ch[rb + FD + c]) = hh;
                }
            }
        }
    }

    float* sums = mode1 ? g_sv : g_su;
    #pragma unroll
    for (int mt = 0; mt < 4; mt++)
        #pragma unroll
        for (int h = 0; h < 2; h++) {
            float v = rs[mt][h];
            v += __shfl_xor_sync(0xffffffffu, v, 1);
            v += __shfl_xor_sync(0xffffffffu, v, 2);
            if ((lane & 3) == 0) {
                const int row = by * 128 + wm * 64 + mt * 16 + (lane >> 2) + h * 8;
                atomicAdd(&sums[row], v);
            }
        }
}

// ---------------------------------------------------------------------------
// GEMM3 (pure bf16 single-pass, R14-proven): 128(M) x 64(N), K=4096, BK=64,
// 4-stage. out = acc - alpha*su[row] - beta*sv[col]
// ---------------------------------------------------------------------------
__global__ void __launch_bounds__(256, 2)
tv_gemm3(float* __restrict__ out,
         const float* __restrict__ alpha_p,
         const float* __restrict__ beta_p)
{
    constexpr int K = K2;
    constexpr int T = K / 64;          // 64 chunks

    extern __shared__ __align__(1024) char smem[];
    const uint32_t sb = smem_u32(smem);
    const int tid  = threadIdx.x;
    const int lane = tid & 31, wid = tid >> 5;
    const int wm = wid >> 1, wn = wid & 1;          // 4 x 2 warp grid (32x32 warp tile)

    const int bx = blockIdx.x;                      // 8 N-tiles
    const int by = blockIdx.y;                      // 32 M-tiles

    const __nv_bfloat16* Ahi = g_Ah + (size_t)by * 128 * K;
    const __nv_bfloat16* Bhi = g_Ch + (size_t)bx * 64 * K;

    float acc[2][4][4];
    #pragma unroll
    for (int a = 0; a < 2; a++)
        #pragma unroll
        for (int b = 0; b < 4; b++)
            #pragma unroll
            for (int c = 0; c < 4; c++) acc[a][b][c] = 0.0f;

    // stage: [A 128x128B | B 64x128B] = 24KB
    auto load_tiles = [&](int i) {
        const int k0 = i << 6;
        const uint32_t base = sb + (i & 3) * 24576;
        #pragma unroll
        for (int it = 0; it < 4; it++) {            // A: 1024 chunk-slots
            const int idx = (it << 8) + tid;
            const int r = idx >> 3, c = idx & 7;
            const uint32_t sw = (uint32_t)((c ^ (r & 7)) << 4);
            cp16(base + r * 128 + sw, Ahi + (size_t)r * K + k0 + (c << 3));
        }
        #pragma unroll
        for (int it = 0; it < 2; it++) {            // B: 512 chunk-slots
            const int idx = (it << 8) + tid;
            const int r = idx >> 3, c = idx & 7;
            const uint32_t sw = (uint32_t)((c ^ (r & 7)) << 4);
            cp16(base + 16384 + r * 128 + sw, Bhi + (size_t)r * K + k0 + (c << 3));
        }
    };

    load_tiles(0); cp_commit();
    load_tiles(1); cp_commit();
    load_tiles(2); cp_commit();

    for (int i = 0; i < T; i++) {
        if (i + 3 < T)      { load_tiles(i + 3); cp_commit(); cp_wait<3>(); }
        else if (i + 2 < T) { cp_wait<2>(); }
        else if (i + 1 < T) { cp_wait<1>(); }
        else                { cp_wait<0>(); }
        __syncthreads();

        const uint32_t Ab = sb + (i & 3) * 24576;
        const uint32_t Bb = Ab + 16384;

        #pragma unroll
        for (int ks = 0; ks < 4; ks++) {
            uint32_t afr[2][4], bfr[2][4];
            #pragma unroll
            for (int mt = 0; mt < 2; mt++) {
                const int r  = wm * 32 + mt * 16 + (lane & 15);
                const int cb = (ks << 1) + (lane >> 4);
                ldsm4(afr[mt], Ab + r * 128 + ((cb ^ (r & 7)) << 4));
            }
            #pragma unroll
            for (int np = 0; np < 2; np++) {
                const int g  = lane >> 3;
                const int r  = wn * 32 + np * 16 + ((g & 2) << 2) + (lane & 7);
                const int cb = (ks << 1) + (g & 1);
                ldsm4(bfr[np], Bb + r * 128 + ((cb ^ (r & 7)) << 4));
            }
            #pragma unroll
            for (int mt = 0; mt < 2; mt++)
                #pragma unroll
                for (int nt = 0; nt < 4; nt++)
                    mma16816(acc[mt][nt], afr[mt],
                             bfr[nt >> 1][(nt & 1) * 2], bfr[nt >> 1][(nt & 1) * 2 + 1]);
        }
        __syncthreads();
    }

    const float al_ = *alpha_p, be = *beta_p;

    #pragma unroll
    for (int mt = 0; mt < 2; mt++) {
        const size_t r1 = (size_t)by * 128 + wm * 32 + mt * 16 + (lane >> 2);
        const size_t r2 = r1 + 8;
        const float s1 = al_ * g_su[r1], s2 = al_ * g_su[r2];
        #pragma unroll
        for (int nt = 0; nt < 4; nt++) {
            const int c = bx * 64 + wn * 32 + nt * 8 + ((lane & 3) << 1);
            const float sv0 = be * g_sv[c], sv1 = be * g_sv[c + 1];
            const float* d = acc[mt][nt];
            float2 o1 = make_float2(d[0] - s1 - sv0, d[1] - s1 - sv1);
            float2 o2 = make_float2(d[2] - s2 - sv0, d[3] - s2 - sv1);
            *reinterpret_cast<float2*>(&out[r1 * PD + c]) = o1;
            *reinterpret_cast<float2*>(&out[r2 * PD + c]) = o2;
        }
    }
}

// ---------------------------------------------------------------------------
extern "C" void kernel_launch(void* const* d_in, const int* in_sizes, int n_in,
                              void* d_out, int out_size)
{
    const float* x      = (const float*)d_in[0];  // [4096, 1024]
    const float* feats  = (const float*)d_in[1];  // [2048, 1024]
    const float* protos = (const float*)d_in[2];  // [512, 1024]
    const float* alpha  = (const float*)d_in[3];
    const float* beta   = (const float*)d_in[4];
    const float* theta  = (const float*)d_in[5];
    float* out = (float*)d_out;                   // [4096, 512]

    cudaFuncSetAttribute(tv_gemm12, cudaFuncAttributeMaxDynamicSharedMemorySize, SMEM12);
    cudaFuncSetAttribute(tv_gemm3,  cudaFuncAttributeMaxDynamicSharedMemorySize, SMEM3);

    constexpr int NTOT = BD * ID + FD * ID + PD * ID;   // multiple of 2048
    split_all<<<NTOT / 2048, 256>>>(x, feats, protos);

    tv_gemm12<<<576, 256, SMEM12>>>(alpha, beta, theta);
    tv_gemm3<<<dim3(8, 32), 256, SMEM3>>>(out, alpha, beta);
}

// round 17
// speedup vs baseline: 3.9776x; 1.0081x over previous
#include <cuda_runtime.h>
#include <cuda_bf16.h>
#include <cstdint>

#define BD 4096
#define ID 1024
#define PD 512
#define FD 2048
#define K2 4096

#define SMEM12 (3 * 32768)   // 3 stages x (16KB A + 16KB B)
#define SMEM3  (3 * 32768)   // 3 stages x (16KB A + 16KB B)

// ---------------- scratch (device globals; allocation-free) ----------------
__device__ __align__(256) __nv_bfloat16 g_xh[(size_t)BD*ID];
__device__ __align__(256) __nv_bfloat16 g_fh[(size_t)FD*ID];
__device__ __align__(256) __nv_bfloat16 g_ph[(size_t)PD*ID];
__device__ __align__(256) __nv_bfloat16 g_Ah[(size_t)BD*K2];  // [u^2 | u]
__device__ __align__(256) __nv_bfloat16 g_Ch[(size_t)PD*K2];  // [th*v^2+al*v | be*v^2]
__device__ float g_su[BD];   // raw sum_f u^2
__device__ float g_sv[PD];   // raw sum_f v^2

// ---------------- PTX helpers ----------------
__device__ __forceinline__ uint32_t smem_u32(const void* p) {
    uint32_t a;
    asm("{ .reg .u64 t; cvta.to.shared.u64 t, %1; cvt.u32.u64 %0, t; }" : "=r"(a) : "l"(p));
    return a;
}
__device__ __forceinline__ void cp16(uint32_t dst, const void* src) {
    asm volatile("cp.async.cg.shared.global [%0], [%1], 16;" :: "r"(dst), "l"(src));
}
__device__ __forceinline__ void cp_commit() { asm volatile("cp.async.commit_group;" ::: "memory"); }
template<int N> __device__ __forceinline__ void cp_wait() {
    asm volatile("cp.async.wait_group %0;" :: "n"(N) : "memory");
}
__device__ __forceinline__ void ldsm4(uint32_t (&r)[4], uint32_t addr) {
    asm volatile("ldmatrix.sync.aligned.m8n8.x4.shared.b16 {%0,%1,%2,%3}, [%4];"
        : "=r"(r[0]), "=r"(r[1]), "=r"(r[2]), "=r"(r[3]) : "r"(addr));
}
__device__ __forceinline__ void mma16816(float* d, const uint32_t* a, uint32_t b0, uint32_t b1) {
    asm volatile("mma.sync.aligned.m16n8k16.row.col.f32.bf16.bf16.f32 "
        "{%0,%1,%2,%3}, {%4,%5,%6,%7}, {%8,%9}, {%0,%1,%2,%3};"
        : "+f"(d[0]), "+f"(d[1]), "+f"(d[2]), "+f"(d[3])
        : "r"(a[0]), "r"(a[1]), "r"(a[2]), "r"(a[3]), "r"(b0), "r"(b1));
}

// ---------------- vectorized bf16 conversion + accumulator zero ----------
__global__ __launch_bounds__(256) void split_all(const float* __restrict__ x,
                                                 const float* __restrict__ f,
                                                 const float* __restrict__ p)
{
    const int t = blockIdx.x * 256 + threadIdx.x;
    const size_t i = (size_t)t * 8;
    constexpr size_t N1 = (size_t)BD * ID;
    constexpr size_t N2 = N1 + (size_t)FD * ID;
    const float* src; __nv_bfloat16* hp; size_t j;
    if (i < N1)      { j = i;      src = x; hp = g_xh; }
    else if (i < N2) { j = i - N1; src = f; hp = g_fh; }
    else             { j = i - N2; src = p; hp = g_ph; }

    float4 v0 = *reinterpret_cast<const float4*>(src + j);
    float4 v1 = *reinterpret_cast<const float4*>(src + j + 4);
    float vv[8] = {v0.x, v0.y, v0.z, v0.w, v1.x, v1.y, v1.z, v1.w};
    __nv_bfloat16 hh[8];
    #pragma unroll
    for (int k = 0; k < 8; k++) hh[k] = __float2bfloat16(vv[k]);
    *reinterpret_cast<uint4*>(hp + j) = *reinterpret_cast<const uint4*>(hh);

    if (t < BD) g_su[t] = 0.0f;
    if (t < PD) g_sv[t] = 0.0f;
}

// ---------------------------------------------------------------------------
// Fused GEMM1+GEMM2: 128x128xBK64, single pure-bf16 pass, K=1024 (16 chunks).
// bid <  512 : MODE0  x @ f^T -> relu -> g_Ah [u^2|u], atomic sum u^2
// bid >= 512 : MODE1  p @ f^T -> relu -> g_Ch, atomic sum v^2
// ---------------------------------------------------------------------------
__global__ void __launch_bounds__(256, 2)
tv_gemm12(const float* __restrict__ alpha_p,
          const float* __restrict__ beta_p,
          const float* __restrict__ theta_p)
{
    constexpr int K = ID;
    constexpr int T = K / 64;          // 16 chunks

    extern __shared__ __align__(1024) char smem[];
    const uint32_t sb = smem_u32(smem);
    const int tid  = threadIdx.x;
    const int lane = tid & 31, wid = tid >> 5;
    const int wm = wid >> 2, wn = wid & 3;          // 2 x 4 warp grid

    const int bid   = blockIdx.x;
    const int mode1 = (bid >= 512);
    const int lbid  = mode1 ? bid - 512 : bid;
    const int bx    = lbid & 15;
    const int by    = lbid >> 4;

    const __nv_bfloat16* Ahi = (mode1 ? g_ph : g_xh) + (size_t)by * 128 * K;
    const __nv_bfloat16* Bhi = g_fh + (size_t)bx * 128 * K;

    float acc[4][4][4];
    #pragma unroll
    for (int a = 0; a < 4; a++)
        #pragma unroll
        for (int b = 0; b < 4; b++)
            #pragma unroll
            for (int c = 0; c < 4; c++) acc[a][b][c] = 0.0f;

    auto load_tiles = [&](int i) {
        const int k0 = i << 6;
        const uint32_t base = sb + (i % 3) * 32768;
        #pragma unroll
        for (int it = 0; it < 4; it++) {
            const int idx = (it << 8) + tid;          // 0..1023
            const int r = idx >> 3, c = idx & 7;
            const uint32_t sw = (uint32_t)((c ^ (r & 7)) << 4);
            cp16(base + r * 128 + sw,         Ahi + (size_t)r * K + k0 + (c << 3));
            cp16(base + 16384 + r * 128 + sw, Bhi + (size_t)r * K + k0 + (c << 3));
        }
    };

    load_tiles(0); cp_commit();
    load_tiles(1); cp_commit();

    for (int i = 0; i < T; i++) {
        if (i + 2 < T)      { load_tiles(i + 2); cp_commit(); cp_wait<2>(); }
        else if (i + 1 < T) { cp_wait<1>(); }
        else                { cp_wait<0>(); }
        __syncthreads();

        const uint32_t Ab = sb + (i % 3) * 32768;
        const uint32_t Bb = Ab + 16384;

        #pragma unroll
        for (int ks = 0; ks < 4; ks++) {
            uint32_t afr[4][4], bfr[2][4];
            #pragma unroll
            for (int mt = 0; mt < 4; mt++) {
                const int r  = wm * 64 + mt * 16 + (lane & 15);
                const int cb = (ks << 1) + (lane >> 4);
                ldsm4(afr[mt], Ab + r * 128 + ((cb ^ (r & 7)) << 4));
            }
            #pragma unroll
            for (int np = 0; np < 2; np++) {
                const int g  = lane >> 3;
                const int r  = wn * 32 + np * 16 + ((g & 2) << 2) + (lane & 7);
                const int cb = (ks << 1) + (g & 1);
                ldsm4(bfr[np], Bb + r * 128 + ((cb ^ (r & 7)) << 4));
            }
            #pragma unroll
            for (int mt = 0; mt < 4; mt++)
                #pragma unroll
                for (int nt = 0; nt < 4; nt++)
                    mma16816(acc[mt][nt], afr[mt],
                             bfr[nt >> 1][(nt & 1) * 2], bfr[nt >> 1][(nt & 1) * 2 + 1]);
        }
        __syncthreads();
    }

    // ---------------- epilogue: stores + fused row-sum atomics -------------
    float al_ = 0.f, be = 0.f, th = 0.f;
    if (mode1) { al_ = *alpha_p; be = *beta_p; th = *theta_p; }

    float rs[4][2];
    #pragma unroll
    for (int mt = 0; mt < 4; mt++) { rs[mt][0] = 0.0f; rs[mt][1] = 0.0f; }

    #pragma unroll
    for (int mt = 0; mt < 4; mt++) {
        const size_t rbase = (size_t)by * 128 + wm * 64 + mt * 16 + (lane >> 2);
        #pragma unroll
        for (int nt = 0; nt < 4; nt++) {
            const int c = bx * 128 + wn * 32 + nt * 8 + ((lane & 3) << 1);
            #pragma unroll
            for (int h = 0; h < 2; h++) {
                const float v0 = fmaxf(acc[mt][nt][h * 2 + 0], 0.0f);
                const float v1 = fmaxf(acc[mt][nt][h * 2 + 1], 0.0f);
                const float q0 = v0 * v0, q1 = v1 * v1;
                rs[mt][h] += q0 + q1;
                const size_t rb = (rbase + h * 8) * (size_t)K2;
                __nv_bfloat162 hh;
                if (!mode1) {
                    hh.x = __float2bfloat16(q0); hh.y = __float2bfloat16(q1);
                    *reinterpret_cast<__nv_bfloat162*>(&g_Ah[rb + c]) = hh;
                    hh.x = __float2bfloat16(v0); hh.y = __float2bfloat16(v1);
                    *reinterpret_cast<__nv_bfloat162*>(&g_Ah[rb + FD + c]) = hh;
                } else {
                    hh.x = __float2bfloat16(fmaf(th, q0, al_ * v0));
                    hh.y = __float2bfloat16(fmaf(th, q1, al_ * v1));
                    *reinterpret_cast<__nv_bfloat162*>(&g_Ch[rb + c]) = hh;
                    hh.x = __float2bfloat16(be * q0);
                    hh.y = __float2bfloat16(be * q1);
                    *reinterpret_cast<__nv_bfloat162*>(&g_Ch[rb + FD + c]) = hh;
                }
            }
        }
    }

    float* sums = mode1 ? g_sv : g_su;
    #pragma unroll
    for (int mt = 0; mt < 4; mt++)
        #pragma unroll
        for (int h = 0; h < 2; h++) {
            float v = rs[mt][h];
            v += __shfl_xor_sync(0xffffffffu, v, 1);
            v += __shfl_xor_sync(0xffffffffu, v, 2);
            if ((lane & 3) == 0) {
                const int row = by * 128 + wm * 64 + mt * 16 + (lane >> 2) + h * 8;
                atomicAdd(&sums[row], v);
            }
        }
}

// ---------------------------------------------------------------------------
// GEMM3 (128x128 tiles, GEMM12-proven mainloop, K=4096): grid 4 x 32.
// L2 traffic: A 4x64MB + B 32x4MB = 384 MB (vs 640 MB at 128x64 tiles).
// out = acc - alpha*su[row] - beta*sv[col]
// ---------------------------------------------------------------------------
__global__ void __launch_bounds__(256, 2)
tv_gemm3(float* __restrict__ out,
         const float* __restrict__ alpha_p,
         const float* __restrict__ beta_p)
{
    constexpr int K = K2;
    constexpr int T = K / 64;          // 64 chunks

    extern __shared__ __align__(1024) char smem[];
    const uint32_t sb = smem_u32(smem);
    const int tid  = threadIdx.x;
    const int lane = tid & 31, wid = tid >> 5;
    const int wm = wid >> 2, wn = wid & 3;          // 2 x 4 warp grid (64x32 warp tile)

    const int bx = blockIdx.x;                      // 4 N-tiles (128 cols each)
    const int by = blockIdx.y;                      // 32 M-tiles

    const __nv_bfloat16* Ahi = g_Ah + (size_t)by * 128 * K;
    const __nv_bfloat16* Bhi = g_Ch + (size_t)bx * 128 * K;

    float acc[4][4][4];
    #pragma unroll
    for (int a = 0; a < 4; a++)
        #pragma unroll
        for (int b = 0; b < 4; b++)
            #pragma unroll
            for (int c = 0; c < 4; c++) acc[a][b][c] = 0.0f;

    auto load_tiles = [&](int i) {
        const int k0 = i << 6;
        const uint32_t base = sb + (i % 3) * 32768;
        #pragma unroll
        for (int it = 0; it < 4; it++) {
            const int idx = (it << 8) + tid;          // 0..1023
            const int r = idx >> 3, c = idx & 7;
            const uint32_t sw = (uint32_t)((c ^ (r & 7)) << 4);
            cp16(base + r * 128 + sw,         Ahi + (size_t)r * K + k0 + (c << 3));
            cp16(base + 16384 + r * 128 + sw, Bhi + (size_t)r * K + k0 + (c << 3));
        }
    };

    load_tiles(0); cp_commit();
    load_tiles(1); cp_commit();

    for (int i = 0; i < T; i++) {
        if (i + 2 < T)      { load_tiles(i + 2); cp_commit(); cp_wait<2>(); }
        else if (i + 1 < T) { cp_wait<1>(); }
        else                { cp_wait<0>(); }
        __syncthreads();

        const uint32_t Ab = sb + (i % 3) * 32768;
        const uint32_t Bb = Ab + 16384;

        #pragma unroll
        for (int ks = 0; ks < 4; ks++) {
            uint32_t afr[4][4], bfr[2][4];
            #pragma unroll
            for (int mt = 0; mt < 4; mt++) {
                const int r  = wm * 64 + mt * 16 + (lane & 15);
                const int cb = (ks << 1) + (lane >> 4);
                ldsm4(afr[mt], Ab + r * 128 + ((cb ^ (r & 7)) << 4));
            }
            #pragma unroll
            for (int np = 0; np < 2; np++) {
                const int g  = lane >> 3;
                const int r  = wn * 32 + np * 16 + ((g & 2) << 2) + (lane & 7);
                const int cb = (ks << 1) + (g & 1);
                ldsm4(bfr[np], Bb + r * 128 + ((cb ^ (r & 7)) << 4));
            }
            #pragma unroll
            for (int mt = 0; mt < 4; mt++)
                #pragma unroll
                for (int nt = 0; nt < 4; nt++)
                    mma16816(acc[mt][nt], afr[mt],
                             bfr[nt >> 1][(nt & 1) * 2], bfr[nt >> 1][(nt & 1) * 2 + 1]);
        }
        __syncthreads();
    }

    const float al_ = *alpha_p, be = *beta_p;

    #pragma unroll
    for (int mt = 0; mt < 4; mt++) {
        const size_t r1 = (size_t)by * 128 + wm * 64 + mt * 16 + (lane >> 2);
        const size_t r2 = r1 + 8;
        const float s1 = al_ * g_su[r1], s2 = al_ * g_su[r2];
        #pragma unroll
        for (int nt = 0; nt < 4; nt++) {
            const int c = bx * 128 + wn * 32 + nt * 8 + ((lane & 3) << 1);
            const float sv0 = be * g_sv[c], sv1 = be * g_sv[c + 1];
            const float* d = acc[mt][nt];
            float2 o1 = make_float2(d[0] - s1 - sv0, d[1] - s1 - sv1);
            float2 o2 = make_float2(d[2] - s2 - sv0, d[3] - s2 - sv1);
            *reinterpret_cast<float2*>(&out[r1 * PD + c]) = o1;
            *reinterpret_cast<float2*>(&out[r2 * PD + c]) = o2;
        }
    }
}

// ---------------------------------------------------------------------------
extern "C" void kernel_launch(void* const* d_in, const int* in_sizes, int n_in,
                              void* d_out, int out_size)
{
    const float* x      = (const float*)d_in[0];  // [4096, 1024]
    const float* feats  = (const float*)d_in[1];  // [2048, 1024]
    const float* protos = (const float*)d_in[2];  // [512, 1024]
    const float* alpha  = (const float*)d_in[3];
    const float* beta   = (const float*)d_in[4];
    const float* theta  = (const float*)d_in[5];
    float* out = (float*)d_out;                   // [4096, 512]

    cudaFuncSetAttribute(tv_gemm12, cudaFuncAttributeMaxDynamicSharedMemorySize, SMEM12);
    cudaFuncSetAttribute(tv_gemm3,  cudaFuncAttributeMaxDynamicSharedMemorySize, SMEM3);

    constexpr int NTOT = BD * ID + FD * ID + PD * ID;   // multiple of 2048
    split_all<<<NTOT / 2048, 256>>>(x, feats, protos);

    tv_gemm12<<<576, 256, SMEM12>>>(alpha, beta, theta);
    tv_gemm3<<<dim3(4, 32), 256, SMEM3>>>(out, alpha, beta);
}